// round 1
// baseline (speedup 1.0000x reference)
#include <cuda_runtime.h>
#include <cuda_bf16.h>
#include <cstdint>

// ---------------------------------------------------------------------------
// Problem constants
// ---------------------------------------------------------------------------
#define BB   128
#define TT   20
#define TS   19          // T-1 decode steps
#define NN   49
#define VOCAB 10000
#define EMB  512
#define HD   1024
#define VD   512
#define ATT  512
#define G4   4096        // 4*HD

// ---------------------------------------------------------------------------
// Scratch: one big device global (no runtime allocation allowed)
// ---------------------------------------------------------------------------
// float offsets
#define OFF_VP    ((size_t)0)                              // [B*N, HD]      6,422,528
#define OFF_UV    (OFF_VP   + (size_t)BB*NN*HD)            // [B*N, ATT]     3,211,264
#define OFF_FM    (OFF_UV   + (size_t)BB*NN*ATT)           // [B, HD]
#define OFF_H1    (OFF_FM   + (size_t)BB*HD)               // 2 x [B,HD]
#define OFF_C1    (OFF_H1   + (size_t)2*BB*HD)
#define OFF_C2    (OFF_C1   + (size_t)2*BB*HD)
#define OFF_H2A   (OFF_C2   + (size_t)2*BB*HD)             // [T, B, HD] (20 slots)
#define OFF_EMBX  (OFF_H2A  + (size_t)TT*BB*HD)            // [19,B,EMB]
#define OFF_G1X   (OFF_EMBX + (size_t)TS*BB*EMB)           // [19,B,4096]
#define OFF_W1    (OFF_G1X  + (size_t)TS*BB*G4)            // [4096,2048]
#define OFF_W2    (OFF_W1   + (size_t)G4*2048)             // [4096,2048]
#define OFF_B1    (OFF_W2   + (size_t)G4*2048)             // [4096]
#define OFF_B2    (OFF_B1   + (size_t)G4)                  // [4096]
#define OFF_X1    (OFF_B2   + (size_t)G4)                  // [B,2048]
#define OFF_X2    (OFF_X1   + (size_t)BB*2048)             // [B,2048]
#define OFF_G     (OFF_X2   + (size_t)BB*2048)             // [B,4096]
#define OFF_WHP   (OFF_G    + (size_t)BB*G4)               // [4,B,ATT]
#define OFF_P     (OFF_WHP  + (size_t)4*BB*ATT)            // [19,B,EMB]
#define BUF_TOTAL (OFF_P    + (size_t)TS*BB*EMB)

__device__ float g_buf[BUF_TOTAL];

__device__ __forceinline__ float sigf(float x) { return 1.f / (1.f + expf(-x)); }

// ---------------------------------------------------------------------------
// Generic SGEMM: C[M,N] = A[M,K] * W[N,K]^T   (both row-major, K contiguous)
// BM=128, BN=32, BK=32, TM=8, TN=4, 128 threads.
// MODE 0: C = acc (+bias[n] if bias != null); splitK partial store if gridDim.z>1
// MODE 1: C = tanh(acc + bias[n])
// MODE 2: C = acc + bias[n] + add[m*N+n]
// MODE 3: logits permuted store: out[(b*19+t)*VOCAB + n], row m = t*128+b
// ---------------------------------------------------------------------------
template <int MODE>
__global__ void __launch_bounds__(128, 1)
gemm_tile(const float* __restrict__ A, int lda,
          const float* __restrict__ W, int ldw,
          float* __restrict__ C, int N, int K,
          const float* __restrict__ bias,
          const float* __restrict__ add)
{
    __shared__ float As[32][132];   // [k][m], row = 132 floats = 528B (16B aligned)
    __shared__ float Ws[32][36];    // [k][n], row = 144B (16B aligned)

    const int tid = threadIdx.x;
    const int n0  = blockIdx.x * 32;
    const int m0  = blockIdx.y * 128;
    const int kchunk = K / gridDim.z;
    const int kbeg   = blockIdx.z * kchunk;

    const float* Ab = A + (size_t)m0 * lda;

    const int a_c = tid & 7;     // A load: col4 group
    const int a_r = tid >> 3;    // A load: row base (0..15)
    const int ty  = tid >> 3;    // compute: row group (0..15) -> m = ty*8+i
    const int tx  = tid & 7;     // compute: col group (0..7)  -> n = tx*4+j

    float acc[8][4];
#pragma unroll
    for (int i = 0; i < 8; i++)
#pragma unroll
        for (int j = 0; j < 4; j++) acc[i][j] = 0.f;

    for (int kb = kbeg; kb < kbeg + kchunk; kb += 32) {
        // load A tile 128x32 (coalesced float4), store transposed
#pragma unroll
        for (int i = 0; i < 8; i++) {
            int r = a_r + 16 * i;
            float4 v = *reinterpret_cast<const float4*>(Ab + (size_t)r * lda + kb + 4 * a_c);
            As[4 * a_c + 0][r] = v.x;
            As[4 * a_c + 1][r] = v.y;
            As[4 * a_c + 2][r] = v.z;
            As[4 * a_c + 3][r] = v.w;
        }
        // load W tile 32x32 (coalesced float4), transposed; guard rows >= N
#pragma unroll
        for (int i = 0; i < 2; i++) {
            int idx = tid + 128 * i;
            int r = idx >> 3, c = idx & 7;
            int n = n0 + r;
            float4 v = make_float4(0.f, 0.f, 0.f, 0.f);
            if (n < N) v = *reinterpret_cast<const float4*>(W + (size_t)n * ldw + kb + 4 * c);
            Ws[4 * c + 0][r] = v.x;
            Ws[4 * c + 1][r] = v.y;
            Ws[4 * c + 2][r] = v.z;
            Ws[4 * c + 3][r] = v.w;
        }
        __syncthreads();
#pragma unroll
        for (int kk = 0; kk < 32; kk++) {
            float4 a0 = *reinterpret_cast<const float4*>(&As[kk][ty * 8]);
            float4 a1 = *reinterpret_cast<const float4*>(&As[kk][ty * 8 + 4]);
            float4 w0 = *reinterpret_cast<const float4*>(&Ws[kk][tx * 4]);
            float av[8] = {a0.x, a0.y, a0.z, a0.w, a1.x, a1.y, a1.z, a1.w};
            float wv[4] = {w0.x, w0.y, w0.z, w0.w};
#pragma unroll
            for (int i = 0; i < 8; i++)
#pragma unroll
                for (int j = 0; j < 4; j++)
                    acc[i][j] = fmaf(av[i], wv[j], acc[i][j]);
        }
        __syncthreads();
    }

    const size_t Mtot = (size_t)gridDim.y * 128;
    float* Cb = C;
    if (gridDim.z > 1) Cb += (size_t)blockIdx.z * Mtot * N;

#pragma unroll
    for (int i = 0; i < 8; i++) {
        int m = m0 + ty * 8 + i;
#pragma unroll
        for (int j = 0; j < 4; j++) {
            int n = n0 + tx * 4 + j;
            if (n >= N) continue;
            float v = acc[i][j];
            if (MODE == 1) {
                v = tanhf(v + bias[n]);
            } else if (MODE == 2) {
                v += bias[n] + add[(size_t)m * N + n];
            } else if (MODE == 0) {
                if (bias) v += bias[n];
            }
            if (MODE == 3) {
                int b = m & 127, t = m >> 7;
                Cb[((size_t)b * TS + t) * VOCAB + n] = v;
            } else {
                Cb[(size_t)m * N + n] = v;
            }
        }
    }
}

// ---------------------------------------------------------------------------
// Prep kernels
// ---------------------------------------------------------------------------
__global__ void build_wcat_kernel(float* __restrict__ dst,
                                  const float* __restrict__ Wih, int ld_ih, int coff,
                                  const float* __restrict__ Whh)
{
    int idx = blockIdx.x * 256 + threadIdx.x;
    if (idx >= G4 * 2048) return;
    int n = idx >> 11, k = idx & 2047;
    dst[idx] = (k < 1024) ? Wih[(size_t)n * ld_ih + coff + k]
                          : Whh[(size_t)n * 1024 + (k - 1024)];
}

__global__ void add_bias_kernel(float* __restrict__ dst,
                                const float* __restrict__ a,
                                const float* __restrict__ b, int n)
{
    int i = blockIdx.x * 256 + threadIdx.x;
    if (i < n) dst[i] = a[i] + b[i];
}

__global__ void emb_gather_kernel(float* __restrict__ dst,
                                  const float* __restrict__ embW,
                                  const int* __restrict__ y)
{
    int idx = blockIdx.x * 256 + threadIdx.x;
    if (idx >= TS * BB * EMB) return;
    int e = idx & 511;
    int b = (idx >> 9) & 127;
    int t = idx >> 16;                       // 512*128 = 65536
    dst[idx] = embW[(size_t)y[b * TT + t] * EMB + e];
}

__global__ void feat_mean_kernel(const float* __restrict__ Vp, float* __restrict__ fm)
{
    int idx = blockIdx.x * 256 + threadIdx.x;
    if (idx >= BB * HD) return;
    int b = idx >> 10, h = idx & 1023;
    const float* p = Vp + (size_t)b * NN * HD + h;
    float s = 0.f;
#pragma unroll 7
    for (int n = 0; n < NN; n++) s += p[n * HD];
    fm[idx] = s * (1.f / 49.f);
}

// ---------------------------------------------------------------------------
// Attention: per-b block. Sums wh split-K partials, computes e, softmax, ctx.
// Writes xcat1[b] = [ctx | h1].
// ---------------------------------------------------------------------------
__global__ void attn_kernel(const float* __restrict__ Vp,
                            const float* __restrict__ Uv,
                            const float* __restrict__ whp,
                            const float* __restrict__ attv,
                            const float* __restrict__ h1cur,
                            float* __restrict__ xcat1)
{
    int b = blockIdx.x, tid = threadIdx.x;
    __shared__ float s_wh[ATT];
    __shared__ float s_e[NN];

    for (int a = tid; a < ATT; a += 256) {
        int o = b * ATT + a;
        s_wh[a] = whp[o] + whp[BB * ATT + o] + whp[2 * BB * ATT + o] + whp[3 * BB * ATT + o];
    }
    __syncthreads();

    int warp = tid >> 5, lane = tid & 31;
    for (int n = warp; n < NN; n += 8) {
        const float* uv = Uv + ((size_t)b * NN + n) * ATT;
        float s = 0.f;
        for (int a = lane; a < ATT; a += 32) s += tanhf(s_wh[a] + uv[a]) * attv[a];
#pragma unroll
        for (int o = 16; o > 0; o >>= 1) s += __shfl_down_sync(0xffffffffu, s, o);
        if (lane == 0) s_e[n] = s;
    }
    __syncthreads();

    if (tid == 0) {
        float m = -1e30f;
        for (int n = 0; n < NN; n++) m = fmaxf(m, s_e[n]);
        float S = 0.f;
        for (int n = 0; n < NN; n++) { float v = expf(s_e[n] - m); s_e[n] = v; S += v; }
        float inv = 1.f / S;
        for (int n = 0; n < NN; n++) s_e[n] *= inv;
    }
    __syncthreads();

    const float* vpb = Vp + (size_t)b * NN * HD;
    for (int h = tid; h < HD; h += 256) {
        float acc = 0.f;
#pragma unroll 7
        for (int n = 0; n < NN; n++) acc += s_e[n] * vpb[n * HD + h];
        xcat1[b * 2048 + h] = acc;
    }
    for (int h = tid; h < HD; h += 256)
        xcat1[b * 2048 + 1024 + h] = h1cur[b * HD + h];
}

// ---------------------------------------------------------------------------
// LSTM cell elementwise + LayerNorm (fused). Optionally builds xcat2=[h_out|h2cur].
// ---------------------------------------------------------------------------
__global__ void lstm_ln_kernel(const float* __restrict__ gates,
                               const float* __restrict__ cin, float* __restrict__ cout,
                               const float* __restrict__ gam, const float* __restrict__ bet,
                               float* __restrict__ hout,
                               float* __restrict__ xcat2,
                               const float* __restrict__ h2cur)
{
    int b = blockIdx.x, tid = threadIdx.x;
    __shared__ float s_h[HD];
    __shared__ float s_red[64];
    __shared__ float s_mu, s_rstd;

    const float* gb = gates + (size_t)b * G4;
    float sum = 0.f, sq = 0.f;
    for (int h = tid; h < HD; h += 256) {
        float ig = gb[h], fg = gb[1024 + h], gg = gb[2048 + h], og = gb[3072 + h];
        float c = sigf(fg) * cin[b * HD + h] + sigf(ig) * tanhf(gg);
        cout[b * HD + h] = c;
        float hv = sigf(og) * tanhf(c);
        s_h[h] = hv;
        sum += hv; sq += hv * hv;
    }
#pragma unroll
    for (int o = 16; o > 0; o >>= 1) {
        sum += __shfl_down_sync(0xffffffffu, sum, o);
        sq  += __shfl_down_sync(0xffffffffu, sq,  o);
    }
    int warp = tid >> 5, lane = tid & 31;
    if (lane == 0) { s_red[warp] = sum; s_red[32 + warp] = sq; }
    __syncthreads();
    if (tid == 0) {
        float S = 0.f, Q = 0.f;
        for (int w = 0; w < 8; w++) { S += s_red[w]; Q += s_red[32 + w]; }
        float mu = S * (1.f / 1024.f);
        float var = Q * (1.f / 1024.f) - mu * mu;
        s_mu = mu;
        s_rstd = 1.f / sqrtf(var + 1e-5f);
    }
    __syncthreads();
    float mu = s_mu, rstd = s_rstd;
    for (int h = tid; h < HD; h += 256) {
        float v = (s_h[h] - mu) * rstd * gam[h] + bet[h];
        hout[b * HD + h] = v;
        if (xcat2) xcat2[b * 2048 + h] = v;
    }
    if (xcat2)
        for (int h = tid; h < HD; h += 256)
            xcat2[b * 2048 + 1024 + h] = h2cur[b * HD + h];
}

// ---------------------------------------------------------------------------
// Launch
// ---------------------------------------------------------------------------
extern "C" void kernel_launch(void* const* d_in, const int* in_sizes, int n_in,
                              void* d_out, int out_size)
{
    (void)in_sizes; (void)n_in; (void)out_size;
    const float* V      = (const float*)d_in[0];
    const int*   y      = (const int*)  d_in[1];
    const float* embW   = (const float*)d_in[2];
    const float* Vp_W   = (const float*)d_in[3];
    const float* Vp_b   = (const float*)d_in[4];
    const float* attW   = (const float*)d_in[5];
    const float* attU   = (const float*)d_in[6];
    const float* attv   = (const float*)d_in[7];
    const float* l1_Wih = (const float*)d_in[8];
    const float* l1_Whh = (const float*)d_in[9];
    const float* l1_bih = (const float*)d_in[10];
    const float* l1_bhh = (const float*)d_in[11];
    const float* l2_Wih = (const float*)d_in[12];
    const float* l2_Whh = (const float*)d_in[13];
    const float* l2_bih = (const float*)d_in[14];
    const float* l2_bhh = (const float*)d_in[15];
    const float* n1_g   = (const float*)d_in[16];
    const float* n1_b   = (const float*)d_in[17];
    const float* n2_g   = (const float*)d_in[18];
    const float* n2_b   = (const float*)d_in[19];
    const float* ih_W   = (const float*)d_in[20];
    const float* ih_b   = (const float*)d_in[21];
    const float* ic_W   = (const float*)d_in[22];
    const float* ic_b   = (const float*)d_in[23];
    const float* proj_W = (const float*)d_in[24];
    float* out = (float*)d_out;

    float* buf = nullptr;
    cudaGetSymbolAddress((void**)&buf, g_buf);

    float* VP   = buf + OFF_VP;
    float* UV   = buf + OFF_UV;
    float* FM   = buf + OFF_FM;
    float* H1   = buf + OFF_H1;
    float* C1   = buf + OFF_C1;
    float* C2   = buf + OFF_C2;
    float* H2A  = buf + OFF_H2A;
    float* EMBX = buf + OFF_EMBX;
    float* G1X  = buf + OFF_G1X;
    float* W1   = buf + OFF_W1;
    float* W2   = buf + OFF_W2;
    float* B1   = buf + OFF_B1;
    float* B2   = buf + OFF_B2;
    float* X1   = buf + OFF_X1;
    float* X2   = buf + OFF_X2;
    float* G    = buf + OFF_G;
    float* WHP  = buf + OFF_WHP;
    float* P    = buf + OFF_P;

    const int SLOT = BB * HD;      // 131072 floats

    // ---- prep (parallel precompute) ----
    {
        int tot = G4 * 2048;
        build_wcat_kernel<<<(tot + 255) / 256, 256>>>(W1, l1_Wih, 1536, 512, l1_Whh);
        build_wcat_kernel<<<(tot + 255) / 256, 256>>>(W2, l2_Wih, 1024, 0,   l2_Whh);
    }
    add_bias_kernel<<<16, 256>>>(B1, l1_bih, l1_bhh, G4);
    add_bias_kernel<<<16, 256>>>(B2, l2_bih, l2_bhh, G4);
    {
        int tot = TS * BB * EMB;
        emb_gather_kernel<<<(tot + 255) / 256, 256>>>(EMBX, embW, y);
    }

    // Vp = V @ Vp_W^T + Vp_b : [6272,1024]
    gemm_tile<0><<<dim3(HD / 32, NN, 1), 128>>>(V, VD, Vp_W, VD, VP, HD, VD, Vp_b, nullptr);
    // feat_mean
    feat_mean_kernel<<<(BB * HD + 255) / 256, 256>>>(VP, FM);
    // h1 = tanh(fm@ih_W^T + b), c1 = tanh(fm@ic_W^T + b) -> slot 0
    gemm_tile<1><<<dim3(HD / 32, 1, 1), 128>>>(FM, HD, ih_W, HD, H1, HD, HD, ih_b, nullptr);
    gemm_tile<1><<<dim3(HD / 32, 1, 1), 128>>>(FM, HD, ic_W, HD, C1, HD, HD, ic_b, nullptr);
    // Uv = Vp @ attU^T : [6272,512]
    gemm_tile<0><<<dim3(ATT / 32, NN, 1), 128>>>(VP, HD, attU, HD, UV, ATT, HD, nullptr, nullptr);
    // G1x = embx @ l1_Wih[:, :512]^T for all 19 steps : [2432,4096]
    gemm_tile<0><<<dim3(G4 / 32, TS, 1), 128>>>(EMBX, EMB, l1_Wih, 1536, G1X, G4, EMB, nullptr, nullptr);

    // zero initial h2 (slot 0 of H2A) and c2 (slot 0)
    cudaMemsetAsync(H2A, 0, (size_t)SLOT * sizeof(float), 0);
    cudaMemsetAsync(C2, 0, (size_t)SLOT * sizeof(float), 0);

    // ---- sequential decode ----
    for (int t = 0; t < TS; t++) {
        const float* h2c = H2A + (size_t)t * SLOT;
        // wh partials: h2 @ attW^T split-K into 4
        gemm_tile<0><<<dim3(ATT / 32, 1, 4), 128>>>(h2c, HD, attW, HD, WHP, ATT, HD, nullptr, nullptr);
        // attention + ctx -> xcat1 = [ctx | h1]
        attn_kernel<<<BB, 256>>>(VP, UV, WHP, attv, H1 + (size_t)(t & 1) * SLOT, X1);
        // gates1 = xcat1 @ Wcat1^T + bias1 + G1x[t]
        gemm_tile<2><<<dim3(G4 / 32, 1, 1), 128>>>(X1, 2048, W1, 2048, G, G4, 2048,
                                                   B1, G1X + (size_t)t * BB * G4);
        // lstm1 + LN -> h1[(t+1)&1], c1[(t+1)&1], xcat2 = [h1n | h2]
        lstm_ln_kernel<<<BB, 256>>>(G,
                                    C1 + (size_t)(t & 1) * SLOT,
                                    C1 + (size_t)((t + 1) & 1) * SLOT,
                                    n1_g, n1_b,
                                    H1 + (size_t)((t + 1) & 1) * SLOT,
                                    X2, h2c);
        // gates2 = xcat2 @ Wcat2^T + bias2
        gemm_tile<0><<<dim3(G4 / 32, 1, 1), 128>>>(X2, 2048, W2, 2048, G, G4, 2048, B2, nullptr);
        // lstm2 + LN -> H2A[t+1], c2[(t+1)&1]
        lstm_ln_kernel<<<BB, 256>>>(G,
                                    C2 + (size_t)(t & 1) * SLOT,
                                    C2 + (size_t)((t + 1) & 1) * SLOT,
                                    n2_g, n2_b,
                                    H2A + (size_t)(t + 1) * SLOT,
                                    nullptr, nullptr);
    }

    // ---- deferred output projection (parallel over all 19 steps) ----
    // P[t*128+b] = H2A[t+1][b] @ proj_W^T : [2432,512]
    gemm_tile<0><<<dim3(EMB / 32, TS, 1), 128>>>(H2A + SLOT, HD, proj_W, HD, P, EMB, HD,
                                                 nullptr, nullptr);
    // logits = P @ embed_W^T, permuted store to out[b, t, :] : [2432,10000]
    gemm_tile<3><<<dim3((VOCAB + 31) / 32, TS, 1), 128>>>(P, EMB, embW, EMB, out, VOCAB, EMB,
                                                          nullptr, nullptr);
}

// round 2
// speedup vs baseline: 1.1992x; 1.1992x over previous
#include <cuda_runtime.h>
#include <cuda_bf16.h>
#include <cstdint>

// ---------------------------------------------------------------------------
// Problem constants
// ---------------------------------------------------------------------------
#define BB   128
#define TT   20
#define TS   19          // T-1 decode steps
#define NN   49
#define VOCAB 10000
#define EMB  512
#define HD   1024
#define VD   512
#define ATT  512
#define G4   4096        // 4*HD
#define ZK   4           // split-K factor for sequential gates GEMMs

// ---------------------------------------------------------------------------
// Scratch: one big device global (no runtime allocation allowed)
// ---------------------------------------------------------------------------
#define OFF_VP    ((size_t)0)                              // [B*N, HD]
#define OFF_UV    (OFF_VP   + (size_t)BB*NN*HD)            // [B*N, ATT]
#define OFF_FM    (OFF_UV   + (size_t)BB*NN*ATT)           // [B, HD]
#define OFF_H1    (OFF_FM   + (size_t)BB*HD)               // 2 x [B,HD]
#define OFF_C1    (OFF_H1   + (size_t)2*BB*HD)
#define OFF_C2    (OFF_C1   + (size_t)2*BB*HD)
#define OFF_H2A   (OFF_C2   + (size_t)2*BB*HD)             // [T, B, HD]
#define OFF_EMBX  (OFF_H2A  + (size_t)TT*BB*HD)            // [19,B,EMB]
#define OFF_G1X   (OFF_EMBX + (size_t)TS*BB*EMB)           // [19,B,4096]
#define OFF_W1    (OFF_G1X  + (size_t)TS*BB*G4)            // [4096,2048]
#define OFF_W2    (OFF_W1   + (size_t)G4*2048)             // [4096,2048]
#define OFF_B1    (OFF_W2   + (size_t)G4*2048)             // [4096]
#define OFF_B2    (OFF_B1   + (size_t)G4)                  // [4096]
#define OFF_X1    (OFF_B2   + (size_t)G4)                  // [B,2048]
#define OFF_X2    (OFF_X1   + (size_t)BB*2048)             // [B,2048]
#define OFF_GP    (OFF_X2   + (size_t)BB*2048)             // [ZK,B,4096] partials
#define OFF_WHP   (OFF_GP   + (size_t)ZK*BB*G4)            // [4,B,ATT]
#define OFF_P     (OFF_WHP  + (size_t)4*BB*ATT)            // [19,B,EMB]
#define BUF_TOTAL (OFF_P    + (size_t)TS*BB*EMB)

__device__ float g_buf[BUF_TOTAL];

__device__ __forceinline__ float sigf(float x) { return 1.f / (1.f + expf(-x)); }

// packed fp32x2 helpers (sm_103a): 2 IEEE fp32 FMAs per instruction
__device__ __forceinline__ void fma2(unsigned long long& d,
                                     unsigned long long a,
                                     unsigned long long b) {
    asm("fma.rn.f32x2 %0, %1, %2, %0;" : "+l"(d) : "l"(a), "l"(b));
}
__device__ __forceinline__ unsigned long long splat2(float x) {
    unsigned long long r;
    unsigned u = __float_as_uint(x);
    asm("mov.b64 %0, {%1, %1};" : "=l"(r) : "r"(u));
    return r;
}

// ---------------------------------------------------------------------------
// SGEMM: C[M,N] = A[M,K] * W[N,K]^T  (row-major, K contiguous)
// BM=128, BN=32, BK=32, 128 threads; per-thread 8 rows x 4 cols via f32x2
// (row-pairs packed in 64-bit lanes).
// MODE 0: C = acc (+bias[n] if bias); splitK partial store if gridDim.z>1
// MODE 1: C = tanh(acc + bias[n])
// MODE 3: logits permuted store: out[(b*19+t)*VOCAB + n], row m = t*128+b
// ---------------------------------------------------------------------------
template <int MODE>
__global__ void __launch_bounds__(128)
gemm_tile(const float* __restrict__ A, int lda,
          const float* __restrict__ W, int ldw,
          float* __restrict__ C, int N, int K,
          const float* __restrict__ bias)
{
    __shared__ float As[32][132];   // [k][m] transposed
    __shared__ float Ws[32][36];    // [k][n] transposed

    const int tid = threadIdx.x;
    const int n0  = blockIdx.x * 32;
    const int m0  = blockIdx.y * 128;
    const int kchunk = K / gridDim.z;
    const int kbeg   = blockIdx.z * kchunk;

    const float* Ab = A + (size_t)m0 * lda;

    const int a_c = tid & 7;
    const int a_r = tid >> 3;
    const int ty  = tid >> 3;    // row group: rows ty*8 .. ty*8+7
    const int tx  = tid & 7;     // col group: cols tx*4 .. tx*4+3

    unsigned long long acc[4][4];  // [row-pair][col]
#pragma unroll
    for (int i = 0; i < 4; i++)
#pragma unroll
        for (int j = 0; j < 4; j++) acc[i][j] = 0ull;

    for (int kb = kbeg; kb < kbeg + kchunk; kb += 32) {
        // A tile 128x32 coalesced float4, stored transposed
#pragma unroll
        for (int i = 0; i < 8; i++) {
            int r = a_r + 16 * i;
            float4 v = *reinterpret_cast<const float4*>(Ab + (size_t)r * lda + kb + 4 * a_c);
            As[4 * a_c + 0][r] = v.x;
            As[4 * a_c + 1][r] = v.y;
            As[4 * a_c + 2][r] = v.z;
            As[4 * a_c + 3][r] = v.w;
        }
        // W tile 32x32 coalesced float4, transposed; guard rows >= N
#pragma unroll
        for (int i = 0; i < 2; i++) {
            int idx = tid + 128 * i;
            int r = idx >> 3, c = idx & 7;
            int n = n0 + r;
            float4 v = make_float4(0.f, 0.f, 0.f, 0.f);
            if (n < N) v = *reinterpret_cast<const float4*>(W + (size_t)n * ldw + kb + 4 * c);
            Ws[4 * c + 0][r] = v.x;
            Ws[4 * c + 1][r] = v.y;
            Ws[4 * c + 2][r] = v.z;
            Ws[4 * c + 3][r] = v.w;
        }
        __syncthreads();
#pragma unroll
        for (int kk = 0; kk < 32; kk++) {
            // row pairs come packed straight out of shared (16B-aligned)
            double2 a01 = *reinterpret_cast<const double2*>(&As[kk][ty * 8]);
            double2 a23 = *reinterpret_cast<const double2*>(&As[kk][ty * 8 + 4]);
            unsigned long long av[4];
            av[0] = __double_as_longlong(a01.x);
            av[1] = __double_as_longlong(a01.y);
            av[2] = __double_as_longlong(a23.x);
            av[3] = __double_as_longlong(a23.y);
            float4 w = *reinterpret_cast<const float4*>(&Ws[kk][tx * 4]);
            unsigned long long wv[4] = {splat2(w.x), splat2(w.y), splat2(w.z), splat2(w.w)};
#pragma unroll
            for (int i = 0; i < 4; i++)
#pragma unroll
                for (int j = 0; j < 4; j++)
                    fma2(acc[i][j], av[i], wv[j]);
        }
        __syncthreads();
    }

    const size_t Mtot = (size_t)gridDim.y * 128;
    float* Cb = C;
    if (gridDim.z > 1) Cb += (size_t)blockIdx.z * Mtot * N;

#pragma unroll
    for (int i = 0; i < 4; i++) {
        int mA = m0 + ty * 8 + 2 * i;
#pragma unroll
        for (int j = 0; j < 4; j++) {
            int n = n0 + tx * 4 + j;
            if (n >= N) continue;
            float2 p = *reinterpret_cast<float2*>(&acc[i][j]);
            float v0 = p.x, v1 = p.y;
            if (MODE == 1) {
                v0 = tanhf(v0 + bias[n]);
                v1 = tanhf(v1 + bias[n]);
            } else if (MODE == 0) {
                if (bias) { v0 += bias[n]; v1 += bias[n]; }
            }
            if (MODE == 3) {
                int b0 = mA & 127, t0 = mA >> 7;
                int b1 = (mA + 1) & 127, t1 = (mA + 1) >> 7;
                Cb[((size_t)b0 * TS + t0) * VOCAB + n] = v0;
                Cb[((size_t)b1 * TS + t1) * VOCAB + n] = v1;
            } else {
                Cb[(size_t)mA * N + n] = v0;
                Cb[(size_t)(mA + 1) * N + n] = v1;
            }
        }
    }
}

// ---------------------------------------------------------------------------
// Prep kernels
// ---------------------------------------------------------------------------
__global__ void build_wcat_kernel(float* __restrict__ dst,
                                  const float* __restrict__ Wih, int ld_ih, int coff,
                                  const float* __restrict__ Whh)
{
    int idx = blockIdx.x * 256 + threadIdx.x;
    if (idx >= G4 * 2048) return;
    int n = idx >> 11, k = idx & 2047;
    dst[idx] = (k < 1024) ? Wih[(size_t)n * ld_ih + coff + k]
                          : Whh[(size_t)n * 1024 + (k - 1024)];
}

__global__ void add_bias_kernel(float* __restrict__ dst,
                                const float* __restrict__ a,
                                const float* __restrict__ b, int n)
{
    int i = blockIdx.x * 256 + threadIdx.x;
    if (i < n) dst[i] = a[i] + b[i];
}

__global__ void emb_gather_kernel(float* __restrict__ dst,
                                  const float* __restrict__ embW,
                                  const int* __restrict__ y)
{
    int idx = blockIdx.x * 256 + threadIdx.x;
    if (idx >= TS * BB * EMB) return;
    int e = idx & 511;
    int b = (idx >> 9) & 127;
    int t = idx >> 16;
    dst[idx] = embW[(size_t)y[b * TT + t] * EMB + e];
}

__global__ void feat_mean_kernel(const float* __restrict__ Vp, float* __restrict__ fm)
{
    int idx = blockIdx.x * 256 + threadIdx.x;
    if (idx >= BB * HD) return;
    int b = idx >> 10, h = idx & 1023;
    const float* p = Vp + (size_t)b * NN * HD + h;
    float s = 0.f;
#pragma unroll 7
    for (int n = 0; n < NN; n++) s += p[n * HD];
    fm[idx] = s * (1.f / 49.f);
}

// ---------------------------------------------------------------------------
// Attention: per-b block. Sums wh split-K partials, computes e, softmax, ctx.
// Writes xcat1[b] = [ctx | h1].
// ---------------------------------------------------------------------------
__global__ void attn_kernel(const float* __restrict__ Vp,
                            const float* __restrict__ Uv,
                            const float* __restrict__ whp,
                            const float* __restrict__ attv,
                            const float* __restrict__ h1cur,
                            float* __restrict__ xcat1)
{
    int b = blockIdx.x, tid = threadIdx.x;
    __shared__ float s_wh[ATT];
    __shared__ float s_e[NN];

    for (int a = tid; a < ATT; a += 256) {
        int o = b * ATT + a;
        s_wh[a] = whp[o] + whp[BB * ATT + o] + whp[2 * BB * ATT + o] + whp[3 * BB * ATT + o];
    }
    __syncthreads();

    int warp = tid >> 5, lane = tid & 31;
    for (int n = warp; n < NN; n += 8) {
        const float* uv = Uv + ((size_t)b * NN + n) * ATT;
        float s = 0.f;
        for (int a = lane; a < ATT; a += 32) s += tanhf(s_wh[a] + uv[a]) * attv[a];
#pragma unroll
        for (int o = 16; o > 0; o >>= 1) s += __shfl_down_sync(0xffffffffu, s, o);
        if (lane == 0) s_e[n] = s;
    }
    __syncthreads();

    if (tid == 0) {
        float m = -1e30f;
        for (int n = 0; n < NN; n++) m = fmaxf(m, s_e[n]);
        float S = 0.f;
        for (int n = 0; n < NN; n++) { float v = expf(s_e[n] - m); s_e[n] = v; S += v; }
        float inv = 1.f / S;
        for (int n = 0; n < NN; n++) s_e[n] *= inv;
    }
    __syncthreads();

    const float* vpb = Vp + (size_t)b * NN * HD;
    for (int h = tid; h < HD; h += 256) {
        float acc = 0.f;
#pragma unroll 7
        for (int n = 0; n < NN; n++) acc += s_e[n] * vpb[n * HD + h];
        xcat1[b * 2048 + h] = acc;
    }
    for (int h = tid; h < HD; h += 256)
        xcat1[b * 2048 + 1024 + h] = h1cur[b * HD + h];
}

// ---------------------------------------------------------------------------
// LSTM cell + LayerNorm, fused with split-K gate reduction (+bias, +extra).
// gates partials: gp[z][B][4096], z = 0..ZK-1.
// ---------------------------------------------------------------------------
__global__ void lstm_ln_kernel(const float* __restrict__ gp,
                               const float* __restrict__ bias,
                               const float* __restrict__ extra,   // may be null
                               const float* __restrict__ cin, float* __restrict__ cout,
                               const float* __restrict__ gam, const float* __restrict__ bet,
                               float* __restrict__ hout,
                               float* __restrict__ xcat2,
                               const float* __restrict__ h2cur)
{
    const size_t BG = (size_t)BB * G4;
    int b = blockIdx.x, tid = threadIdx.x;
    __shared__ float s_h[HD];
    __shared__ float s_red[64];
    __shared__ float s_mu, s_rstd;

    float sum = 0.f, sq = 0.f;
    for (int h = tid; h < HD; h += 256) {
        float g[4];
#pragma unroll
        for (int q = 0; q < 4; q++) {
            size_t idx = (size_t)b * G4 + q * 1024 + h;
            float v = gp[idx] + gp[BG + idx] + gp[2 * BG + idx] + gp[3 * BG + idx]
                    + bias[q * 1024 + h];
            if (extra) v += extra[idx];
            g[q] = v;
        }
        float c = sigf(g[1]) * cin[b * HD + h] + sigf(g[0]) * tanhf(g[2]);
        cout[b * HD + h] = c;
        float hv = sigf(g[3]) * tanhf(c);
        s_h[h] = hv;
        sum += hv; sq += hv * hv;
    }
#pragma unroll
    for (int o = 16; o > 0; o >>= 1) {
        sum += __shfl_down_sync(0xffffffffu, sum, o);
        sq  += __shfl_down_sync(0xffffffffu, sq,  o);
    }
    int warp = tid >> 5, lane = tid & 31;
    if (lane == 0) { s_red[warp] = sum; s_red[32 + warp] = sq; }
    __syncthreads();
    if (tid == 0) {
        float S = 0.f, Q = 0.f;
        for (int w = 0; w < 8; w++) { S += s_red[w]; Q += s_red[32 + w]; }
        float mu = S * (1.f / 1024.f);
        float var = Q * (1.f / 1024.f) - mu * mu;
        s_mu = mu;
        s_rstd = 1.f / sqrtf(var + 1e-5f);
    }
    __syncthreads();
    float mu = s_mu, rstd = s_rstd;
    for (int h = tid; h < HD; h += 256) {
        float v = (s_h[h] - mu) * rstd * gam[h] + bet[h];
        hout[b * HD + h] = v;
        if (xcat2) xcat2[b * 2048 + h] = v;
    }
    if (xcat2)
        for (int h = tid; h < HD; h += 256)
            xcat2[b * 2048 + 1024 + h] = h2cur[b * HD + h];
}

// ---------------------------------------------------------------------------
// Launch
// ---------------------------------------------------------------------------
extern "C" void kernel_launch(void* const* d_in, const int* in_sizes, int n_in,
                              void* d_out, int out_size)
{
    (void)in_sizes; (void)n_in; (void)out_size;
    const float* V      = (const float*)d_in[0];
    const int*   y      = (const int*)  d_in[1];
    const float* embW   = (const float*)d_in[2];
    const float* Vp_W   = (const float*)d_in[3];
    const float* Vp_b   = (const float*)d_in[4];
    const float* attW   = (const float*)d_in[5];
    const float* attU   = (const float*)d_in[6];
    const float* attv   = (const float*)d_in[7];
    const float* l1_Wih = (const float*)d_in[8];
    const float* l1_Whh = (const float*)d_in[9];
    const float* l1_bih = (const float*)d_in[10];
    const float* l1_bhh = (const float*)d_in[11];
    const float* l2_Wih = (const float*)d_in[12];
    const float* l2_Whh = (const float*)d_in[13];
    const float* l2_bih = (const float*)d_in[14];
    const float* l2_bhh = (const float*)d_in[15];
    const float* n1_g   = (const float*)d_in[16];
    const float* n1_b   = (const float*)d_in[17];
    const float* n2_g   = (const float*)d_in[18];
    const float* n2_b   = (const float*)d_in[19];
    const float* ih_W   = (const float*)d_in[20];
    const float* ih_b   = (const float*)d_in[21];
    const float* ic_W   = (const float*)d_in[22];
    const float* ic_b   = (const float*)d_in[23];
    const float* proj_W = (const float*)d_in[24];
    float* out = (float*)d_out;

    float* buf = nullptr;
    cudaGetSymbolAddress((void**)&buf, g_buf);

    float* VP   = buf + OFF_VP;
    float* UV   = buf + OFF_UV;
    float* FM   = buf + OFF_FM;
    float* H1   = buf + OFF_H1;
    float* C1   = buf + OFF_C1;
    float* C2   = buf + OFF_C2;
    float* H2A  = buf + OFF_H2A;
    float* EMBX = buf + OFF_EMBX;
    float* G1X  = buf + OFF_G1X;
    float* W1   = buf + OFF_W1;
    float* W2   = buf + OFF_W2;
    float* B1   = buf + OFF_B1;
    float* B2   = buf + OFF_B2;
    float* X1   = buf + OFF_X1;
    float* X2   = buf + OFF_X2;
    float* GP   = buf + OFF_GP;
    float* WHP  = buf + OFF_WHP;
    float* P    = buf + OFF_P;

    const int SLOT = BB * HD;

    // ---- prep (parallel precompute) ----
    {
        int tot = G4 * 2048;
        build_wcat_kernel<<<(tot + 255) / 256, 256>>>(W1, l1_Wih, 1536, 512, l1_Whh);
        build_wcat_kernel<<<(tot + 255) / 256, 256>>>(W2, l2_Wih, 1024, 0,   l2_Whh);
    }
    add_bias_kernel<<<16, 256>>>(B1, l1_bih, l1_bhh, G4);
    add_bias_kernel<<<16, 256>>>(B2, l2_bih, l2_bhh, G4);
    {
        int tot = TS * BB * EMB;
        emb_gather_kernel<<<(tot + 255) / 256, 256>>>(EMBX, embW, y);
    }

    // Vp = V @ Vp_W^T + Vp_b : [6272,1024]
    gemm_tile<0><<<dim3(HD / 32, NN, 1), 128>>>(V, VD, Vp_W, VD, VP, HD, VD, Vp_b);
    feat_mean_kernel<<<(BB * HD + 255) / 256, 256>>>(VP, FM);
    gemm_tile<1><<<dim3(HD / 32, 1, 1), 128>>>(FM, HD, ih_W, HD, H1, HD, HD, ih_b);
    gemm_tile<1><<<dim3(HD / 32, 1, 1), 128>>>(FM, HD, ic_W, HD, C1, HD, HD, ic_b);
    // Uv = Vp @ attU^T : [6272,512]
    gemm_tile<0><<<dim3(ATT / 32, NN, 1), 128>>>(VP, HD, attU, HD, UV, ATT, HD, nullptr);
    // G1x = embx @ l1_Wih[:, :512]^T for all 19 steps : [2432,4096]
    gemm_tile<0><<<dim3(G4 / 32, TS, 1), 128>>>(EMBX, EMB, l1_Wih, 1536, G1X, G4, EMB, nullptr);

    cudaMemsetAsync(H2A, 0, (size_t)SLOT * sizeof(float), 0);
    cudaMemsetAsync(C2, 0, (size_t)SLOT * sizeof(float), 0);

    // ---- sequential decode ----
    for (int t = 0; t < TS; t++) {
        const float* h2c = H2A + (size_t)t * SLOT;
        // wh partials: h2 @ attW^T split-K into 4 (summed in attn_kernel)
        gemm_tile<0><<<dim3(ATT / 32, 1, 4), 128>>>(h2c, HD, attW, HD, WHP, ATT, HD, nullptr);
        attn_kernel<<<BB, 256>>>(VP, UV, WHP, attv, H1 + (size_t)(t & 1) * SLOT, X1);
        // gates1 partials: xcat1 @ Wcat1^T, split-K=4 (reduced in lstm_ln)
        gemm_tile<0><<<dim3(G4 / 32, 1, ZK), 128>>>(X1, 2048, W1, 2048, GP, G4, 2048, nullptr);
        lstm_ln_kernel<<<BB, 256>>>(GP, B1, G1X + (size_t)t * BB * G4,
                                    C1 + (size_t)(t & 1) * SLOT,
                                    C1 + (size_t)((t + 1) & 1) * SLOT,
                                    n1_g, n1_b,
                                    H1 + (size_t)((t + 1) & 1) * SLOT,
                                    X2, h2c);
        // gates2 partials: xcat2 @ Wcat2^T, split-K=4
        gemm_tile<0><<<dim3(G4 / 32, 1, ZK), 128>>>(X2, 2048, W2, 2048, GP, G4, 2048, nullptr);
        lstm_ln_kernel<<<BB, 256>>>(GP, B2, nullptr,
                                    C2 + (size_t)(t & 1) * SLOT,
                                    C2 + (size_t)((t + 1) & 1) * SLOT,
                                    n2_g, n2_b,
                                    H2A + (size_t)(t + 1) * SLOT,
                                    nullptr, nullptr);
    }

    // ---- deferred output projection (parallel over all 19 steps) ----
    gemm_tile<0><<<dim3(EMB / 32, TS, 1), 128>>>(H2A + SLOT, HD, proj_W, HD, P, EMB, HD, nullptr);
    gemm_tile<3><<<dim3((VOCAB + 31) / 32, TS, 1), 128>>>(P, EMB, embW, EMB, out, VOCAB, EMB, nullptr);
}

// round 4
// speedup vs baseline: 1.9231x; 1.6036x over previous
#include <cuda_runtime.h>
#include <cuda_bf16.h>
#include <cstdint>

// ---------------------------------------------------------------------------
// Problem constants
// ---------------------------------------------------------------------------
#define BB   128
#define TT   20
#define TS   19
#define NN   49
#define VOCAB 10000
#define NVP  10112       // VOCAB padded to 79*128
#define EMB  512
#define HD   1024
#define VD   512
#define ATT  512
#define G4   4096
#define ZK   4

// ---------------------------------------------------------------------------
// fp32 scratch
// ---------------------------------------------------------------------------
#define OFF_VP    ((size_t)0)                              // [B*N, HD]
#define OFF_UV    (OFF_VP   + (size_t)BB*NN*HD)            // [B*N, ATT]
#define OFF_FM    (OFF_UV   + (size_t)BB*NN*ATT)           // [B, HD]
#define OFF_H1    (OFF_FM   + (size_t)BB*HD)
#define OFF_C1    (OFF_H1   + (size_t)2*BB*HD)
#define OFF_C2    (OFF_C1   + (size_t)2*BB*HD)
#define OFF_H2A   (OFF_C2   + (size_t)2*BB*HD)             // [T, B, HD]
#define OFF_G1X   (OFF_H2A  + (size_t)TT*BB*HD)            // [19,B,4096]
#define OFF_B1    (OFF_G1X  + (size_t)TS*BB*G4)
#define OFF_B2    (OFF_B1   + (size_t)G4)
#define OFF_GP    (OFF_B2   + (size_t)G4)                  // [ZK,B,4096]
#define OFF_WHP   (OFF_GP   + (size_t)ZK*BB*G4)            // [4,B,ATT]
#define OFF_PF    (OFF_WHP  + (size_t)4*BB*ATT)            // [19*B, EMB]
#define BUF_TOTAL (OFF_PF   + (size_t)TS*BB*EMB)
__device__ float g_buf[BUF_TOTAL];

// ---------------------------------------------------------------------------
// bf16 hi/lo scratch (hi at BO_X, lo at BO_X + SZ_X)
// ---------------------------------------------------------------------------
#define SZ_W1   ((size_t)G4*2048)
#define SZ_W2   ((size_t)G4*2048)
#define SZ_EMBW ((size_t)NVP*EMB)
#define SZ_PROJ ((size_t)EMB*HD)
#define SZ_ATTU ((size_t)ATT*HD)
#define SZ_VPW  ((size_t)HD*VD)
#define SZ_WX   ((size_t)G4*EMB)
#define SZ_V    ((size_t)BB*NN*VD)
#define SZ_VPB  ((size_t)BB*NN*HD)
#define SZ_EMBX ((size_t)TS*BB*EMB)
#define SZ_X1   ((size_t)BB*2048)
#define SZ_X2   ((size_t)BB*2048)
#define SZ_H2   ((size_t)TS*BB*HD)
#define SZ_P    ((size_t)TS*BB*EMB)

#define BO_W1   ((size_t)0)
#define BO_W2   (BO_W1   + 2*SZ_W1)
#define BO_EMBW (BO_W2   + 2*SZ_W2)
#define BO_PROJ (BO_EMBW + 2*SZ_EMBW)
#define BO_ATTU (BO_PROJ + 2*SZ_PROJ)
#define BO_VPW  (BO_ATTU + 2*SZ_ATTU)
#define BO_WX   (BO_VPW  + 2*SZ_VPW)
#define BO_V    (BO_WX   + 2*SZ_WX)
#define BO_VPB  (BO_V    + 2*SZ_V)
#define BO_EMBX (BO_VPB  + 2*SZ_VPB)
#define BO_X1   (BO_EMBX + 2*SZ_EMBX)
#define BO_X2   (BO_X1   + 2*SZ_X1)
#define BO_H2   (BO_X2   + 2*SZ_X2)
#define BO_P    (BO_H2   + 2*SZ_H2)
#define BF_TOTAL (BO_P   + 2*SZ_P)
__device__ __nv_bfloat16 g_bf[BF_TOTAL];

__device__ __forceinline__ float sigf(float x) { return 1.f / (1.f + expf(-x)); }

__device__ __forceinline__ void wr_hl(__nv_bfloat16* hi, __nv_bfloat16* lo,
                                      size_t idx, float x) {
    __nv_bfloat16 h = __float2bfloat16(x);
    hi[idx] = h;
    lo[idx] = __float2bfloat16(x - __bfloat162float(h));
}

__device__ __forceinline__ uint32_t smem_u32(const void* p) {
    uint32_t a;
    asm("{ .reg .u64 t; cvta.to.shared.u64 t, %1; cvt.u32.u64 %0, t; }" : "=r"(a) : "l"(p));
    return a;
}

// ---------------------------------------------------------------------------
// HMMA primitives (base-PTX, sm_80+; compile at .target sm_103)
// ---------------------------------------------------------------------------
#define LDSM4(r, a) \
    asm volatile("ldmatrix.sync.aligned.m8n8.x4.shared.b16 {%0,%1,%2,%3}, [%4];" \
        : "=r"((r)[0]), "=r"((r)[1]), "=r"((r)[2]), "=r"((r)[3]) : "r"(a))

#define MMA16816(d, a, b) \
    asm volatile("mma.sync.aligned.m16n8k16.row.col.f32.bf16.bf16.f32 " \
        "{%0,%1,%2,%3}, {%4,%5,%6,%7}, {%8,%9}, {%0,%1,%2,%3};" \
        : "+f"((d)[0]), "+f"((d)[1]), "+f"((d)[2]), "+f"((d)[3]) \
        : "r"((a)[0]), "r"((a)[1]), "r"((a)[2]), "r"((a)[3]), \
          "r"((b)[0]), "r"((b)[1]))

// ---------------------------------------------------------------------------
// HMMA GEMM: C[M,N] = A[M,K] @ B[N,K]^T  via bf16 hi/lo 3-pass split.
// BM=128, BN=128, BK=32, 256 threads (2x4 warps, warp tile 64x32).
// Requires: M%128==0 (grid.y covers M), N%128==0 (B rows padded), K%(32*gridZ)==0.
// MODE 0: fp32 store (+bias), splitK z-offset partials
// MODE 3: logits permuted store with VOCAB bound (row m = t*128+b)
// ---------------------------------------------------------------------------
#define SAK 40   // padded smem row stride (elements)

template <int MODE>
__global__ void __launch_bounds__(256)
hmma_gemm(const __nv_bfloat16* __restrict__ Ahi, const __nv_bfloat16* __restrict__ Alo, int lda,
          const __nv_bfloat16* __restrict__ Bhi, const __nv_bfloat16* __restrict__ Blo, int ldb,
          float* __restrict__ C, int N, int K,
          const float* __restrict__ bias)
{
    __shared__ __nv_bfloat16 sm[4][128][SAK];   // 0=Ah 1=Al 2=Bh 3=Bl

    const int tid  = threadIdx.x;
    const int lane = tid & 31, wid = tid >> 5;
    const int wm = wid & 1;          // 0..1 -> m offset 0/64
    const int wn = wid >> 1;         // 0..3 -> n offset 0/32/64/96
    const int n0 = blockIdx.x * 128, m0 = blockIdx.y * 128;
    const int kchunk = K / gridDim.z;
    const int kbeg   = blockIdx.z * kchunk;

    const int lr = tid >> 2;          // 0..63 (global load row)
    const int lc = (tid & 3) * 8;     // 0/8/16/24 (global load col)

    float acc[4][4][4];
#pragma unroll
    for (int i = 0; i < 4; i++)
#pragma unroll
        for (int j = 0; j < 4; j++)
#pragma unroll
            for (int q = 0; q < 4; q++) acc[i][j][q] = 0.f;

    // ldmatrix source addresses (fixed per thread)
    const int arow = wm * 64 + (lane & 15);
    const int acol = (lane >> 4) * 8;
    const int brow = wn * 32 + ((lane >> 4) * 8) + (lane & 7);
    const int bcol = ((lane >> 3) & 1) * 8;
    uint32_t a_h = smem_u32(&sm[0][arow][acol]);
    uint32_t a_l = smem_u32(&sm[1][arow][acol]);
    uint32_t b_h = smem_u32(&sm[2][brow][bcol]);
    uint32_t b_l = smem_u32(&sm[3][brow][bcol]);

    for (int kb = kbeg; kb < kbeg + kchunk; kb += 32) {
#pragma unroll
        for (int i = 0; i < 2; i++) {
            int r = lr + 64 * i;
            *(uint4*)&sm[0][r][lc] = *(const uint4*)(Ahi + (size_t)(m0 + r) * lda + kb + lc);
            *(uint4*)&sm[1][r][lc] = *(const uint4*)(Alo + (size_t)(m0 + r) * lda + kb + lc);
            *(uint4*)&sm[2][r][lc] = *(const uint4*)(Bhi + (size_t)(n0 + r) * ldb + kb + lc);
            *(uint4*)&sm[3][r][lc] = *(const uint4*)(Blo + (size_t)(n0 + r) * ldb + kb + lc);
        }
        __syncthreads();
#pragma unroll
        for (int s = 0; s < 2; s++) {
            const uint32_t so = s * 16 * 2;   // +16 elements in k
            uint32_t ah[4][4], al[4][4], bh[4][2], bl[4][2];
#pragma unroll
            for (int mt = 0; mt < 4; mt++) {
                LDSM4(ah[mt], a_h + so + mt * 16 * SAK * 2);
                LDSM4(al[mt], a_l + so + mt * 16 * SAK * 2);
            }
#pragma unroll
            for (int p = 0; p < 2; p++) {
                uint32_t r4[4];
                LDSM4(r4, b_h + so + p * 16 * SAK * 2);
                bh[p * 2][0] = r4[0]; bh[p * 2][1] = r4[1];
                bh[p * 2 + 1][0] = r4[2]; bh[p * 2 + 1][1] = r4[3];
                LDSM4(r4, b_l + so + p * 16 * SAK * 2);
                bl[p * 2][0] = r4[0]; bl[p * 2][1] = r4[1];
                bl[p * 2 + 1][0] = r4[2]; bl[p * 2 + 1][1] = r4[3];
            }
#pragma unroll
            for (int mt = 0; mt < 4; mt++)
#pragma unroll
                for (int nt = 0; nt < 4; nt++) {
                    MMA16816(acc[mt][nt], ah[mt], bh[nt]);
                    MMA16816(acc[mt][nt], ah[mt], bl[nt]);
                    MMA16816(acc[mt][nt], al[mt], bh[nt]);
                }
        }
        __syncthreads();
    }

    // epilogue
    const size_t Mtot = (size_t)gridDim.y * 128;
    float* Cb = C + (gridDim.z > 1 ? (size_t)blockIdx.z * Mtot * N : 0);
    const int er = (lane >> 2);          // 0..7
    const int ec = (lane & 3) * 2;       // 0,2,4,6
#pragma unroll
    for (int mt = 0; mt < 4; mt++) {
#pragma unroll
        for (int nt = 0; nt < 4; nt++) {
            int n = n0 + wn * 32 + nt * 8 + ec;
            float b0 = 0.f, b1 = 0.f;
            if (MODE == 0 && bias) { b0 = bias[n]; b1 = bias[n + 1]; }
#pragma unroll
            for (int h = 0; h < 2; h++) {
                int m = m0 + wm * 64 + mt * 16 + er + h * 8;
                float v0 = acc[mt][nt][h * 2 + 0] + b0;
                float v1 = acc[mt][nt][h * 2 + 1] + b1;
                if (MODE == 0) {
                    *(float2*)&Cb[(size_t)m * N + n] = make_float2(v0, v1);
                } else {
                    int b = m & 127, t = m >> 7;
                    float* o = &Cb[((size_t)b * TS + t) * VOCAB + n];
                    if (n < VOCAB) o[0] = v0;
                    if (n + 1 < VOCAB) o[1] = v1;
                }
            }
        }
    }
}

// ---------------------------------------------------------------------------
// fp32 SGEMM (small one-offs: ih/ic init, per-step wh) — f32x2 version
// ---------------------------------------------------------------------------
__device__ __forceinline__ void fma2(unsigned long long& d, unsigned long long a,
                                     unsigned long long b) {
    asm("fma.rn.f32x2 %0, %1, %2, %0;" : "+l"(d) : "l"(a), "l"(b));
}
__device__ __forceinline__ unsigned long long splat2(float x) {
    unsigned long long r;
    unsigned u = __float_as_uint(x);
    asm("mov.b64 %0, {%1, %1};" : "=l"(r) : "r"(u));
    return r;
}

template <int MODE>  // 0: store(+bias, splitK), 1: tanh(acc+bias)
__global__ void __launch_bounds__(128)
gemm_tile(const float* __restrict__ A, int lda,
          const float* __restrict__ W, int ldw,
          float* __restrict__ C, int N, int K,
          const float* __restrict__ bias)
{
    __shared__ float As[32][132];
    __shared__ float Ws[32][36];
    const int tid = threadIdx.x;
    const int n0 = blockIdx.x * 32, m0 = blockIdx.y * 128;
    const int kchunk = K / gridDim.z;
    const int kbeg = blockIdx.z * kchunk;
    const float* Ab = A + (size_t)m0 * lda;
    const int a_c = tid & 7, a_r = tid >> 3;
    const int ty = tid >> 3, tx = tid & 7;

    unsigned long long acc[4][4];
#pragma unroll
    for (int i = 0; i < 4; i++)
#pragma unroll
        for (int j = 0; j < 4; j++) acc[i][j] = 0ull;

    for (int kb = kbeg; kb < kbeg + kchunk; kb += 32) {
#pragma unroll
        for (int i = 0; i < 8; i++) {
            int r = a_r + 16 * i;
            float4 v = *reinterpret_cast<const float4*>(Ab + (size_t)r * lda + kb + 4 * a_c);
            As[4 * a_c + 0][r] = v.x; As[4 * a_c + 1][r] = v.y;
            As[4 * a_c + 2][r] = v.z; As[4 * a_c + 3][r] = v.w;
        }
#pragma unroll
        for (int i = 0; i < 2; i++) {
            int idx = tid + 128 * i;
            int r = idx >> 3, c = idx & 7;
            int n = n0 + r;
            float4 v = make_float4(0.f, 0.f, 0.f, 0.f);
            if (n < N) v = *reinterpret_cast<const float4*>(W + (size_t)n * ldw + kb + 4 * c);
            Ws[4 * c + 0][r] = v.x; Ws[4 * c + 1][r] = v.y;
            Ws[4 * c + 2][r] = v.z; Ws[4 * c + 3][r] = v.w;
        }
        __syncthreads();
#pragma unroll
        for (int kk = 0; kk < 32; kk++) {
            double2 a01 = *reinterpret_cast<const double2*>(&As[kk][ty * 8]);
            double2 a23 = *reinterpret_cast<const double2*>(&As[kk][ty * 8 + 4]);
            unsigned long long av[4] = {__double_as_longlong(a01.x), __double_as_longlong(a01.y),
                                        __double_as_longlong(a23.x), __double_as_longlong(a23.y)};
            float4 w = *reinterpret_cast<const float4*>(&Ws[kk][tx * 4]);
            unsigned long long wv[4] = {splat2(w.x), splat2(w.y), splat2(w.z), splat2(w.w)};
#pragma unroll
            for (int i = 0; i < 4; i++)
#pragma unroll
                for (int j = 0; j < 4; j++) fma2(acc[i][j], av[i], wv[j]);
        }
        __syncthreads();
    }

    const size_t Mtot = (size_t)gridDim.y * 128;
    float* Cb = C + (gridDim.z > 1 ? (size_t)blockIdx.z * Mtot * N : 0);
#pragma unroll
    for (int i = 0; i < 4; i++) {
        int mA = m0 + ty * 8 + 2 * i;
#pragma unroll
        for (int j = 0; j < 4; j++) {
            int n = n0 + tx * 4 + j;
            if (n >= N) continue;
            float2 p = *reinterpret_cast<float2*>(&acc[i][j]);
            float v0 = p.x, v1 = p.y;
            if (MODE == 1) { v0 = tanhf(v0 + bias[n]); v1 = tanhf(v1 + bias[n]); }
            else if (bias) { v0 += bias[n]; v1 += bias[n]; }
            Cb[(size_t)mA * N + n] = v0;
            Cb[(size_t)(mA + 1) * N + n] = v1;
        }
    }
}

// ---------------------------------------------------------------------------
// Prep / conversion kernels
// ---------------------------------------------------------------------------
__global__ void cvt_hl(const float* __restrict__ src, int ld, int rows, int cols,
                       __nv_bfloat16* __restrict__ hi, __nv_bfloat16* __restrict__ lo,
                       int rowsPad)
{
    int idx = blockIdx.x * 256 + threadIdx.x;
    if (idx >= rowsPad * cols) return;
    int r = idx / cols, c = idx - r * cols;
    float x = (r < rows) ? src[(size_t)r * ld + c] : 0.f;
    __nv_bfloat16 h = __float2bfloat16(x);
    hi[idx] = h;
    lo[idx] = __float2bfloat16(x - __bfloat162float(h));
}

__global__ void build_wcat_hl(__nv_bfloat16* __restrict__ hi, __nv_bfloat16* __restrict__ lo,
                              const float* __restrict__ Wih, int ld_ih, int coff,
                              const float* __restrict__ Whh)
{
    int idx = blockIdx.x * 256 + threadIdx.x;
    if (idx >= G4 * 2048) return;
    int n = idx >> 11, k = idx & 2047;
    float x = (k < 1024) ? Wih[(size_t)n * ld_ih + coff + k]
                         : Whh[(size_t)n * 1024 + (k - 1024)];
    __nv_bfloat16 h = __float2bfloat16(x);
    hi[idx] = h;
    lo[idx] = __float2bfloat16(x - __bfloat162float(h));
}

__global__ void add_bias_kernel(float* __restrict__ dst, const float* __restrict__ a,
                                const float* __restrict__ b, int n)
{
    int i = blockIdx.x * 256 + threadIdx.x;
    if (i < n) dst[i] = a[i] + b[i];
}

__global__ void emb_gather_hl(__nv_bfloat16* __restrict__ hi, __nv_bfloat16* __restrict__ lo,
                              const float* __restrict__ embW, const int* __restrict__ y)
{
    int idx = blockIdx.x * 256 + threadIdx.x;
    if (idx >= TS * BB * EMB) return;
    int e = idx & 511;
    int b = (idx >> 9) & 127;
    int t = idx >> 16;
    float x = embW[(size_t)y[b * TT + t] * EMB + e];
    __nv_bfloat16 h = __float2bfloat16(x);
    hi[idx] = h;
    lo[idx] = __float2bfloat16(x - __bfloat162float(h));
}

__global__ void feat_mean_kernel(const float* __restrict__ Vp, float* __restrict__ fm)
{
    int idx = blockIdx.x * 256 + threadIdx.x;
    if (idx >= BB * HD) return;
    int b = idx >> 10, h = idx & 1023;
    const float* p = Vp + (size_t)b * NN * HD + h;
    float s = 0.f;
#pragma unroll 7
    for (int n = 0; n < NN; n++) s += p[n * HD];
    fm[idx] = s * (1.f / 49.f);
}

// ---------------------------------------------------------------------------
// Attention: sums wh partials, e, softmax, ctx; writes X1 = [ctx | h1] hi/lo
// ---------------------------------------------------------------------------
__global__ void attn_kernel(const float* __restrict__ Vp, const float* __restrict__ Uv,
                            const float* __restrict__ whp, const float* __restrict__ attv,
                            const float* __restrict__ h1cur,
                            __nv_bfloat16* __restrict__ x1h, __nv_bfloat16* __restrict__ x1l)
{
    int b = blockIdx.x, tid = threadIdx.x;
    __shared__ float s_wh[ATT];
    __shared__ float s_e[NN];

    for (int a = tid; a < ATT; a += 256) {
        int o = b * ATT + a;
        s_wh[a] = whp[o] + whp[BB * ATT + o] + whp[2 * BB * ATT + o] + whp[3 * BB * ATT + o];
    }
    __syncthreads();

    int warp = tid >> 5, lane = tid & 31;
    for (int n = warp; n < NN; n += 8) {
        const float* uv = Uv + ((size_t)b * NN + n) * ATT;
        float s = 0.f;
        for (int a = lane; a < ATT; a += 32) s += tanhf(s_wh[a] + uv[a]) * attv[a];
#pragma unroll
        for (int o = 16; o > 0; o >>= 1) s += __shfl_down_sync(0xffffffffu, s, o);
        if (lane == 0) s_e[n] = s;
    }
    __syncthreads();

    if (tid == 0) {
        float m = -1e30f;
        for (int n = 0; n < NN; n++) m = fmaxf(m, s_e[n]);
        float S = 0.f;
        for (int n = 0; n < NN; n++) { float v = expf(s_e[n] - m); s_e[n] = v; S += v; }
        float inv = 1.f / S;
        for (int n = 0; n < NN; n++) s_e[n] *= inv;
    }
    __syncthreads();

    const float* vpb = Vp + (size_t)b * NN * HD;
    for (int h = tid; h < HD; h += 256) {
        float acc = 0.f;
#pragma unroll 7
        for (int n = 0; n < NN; n++) acc += s_e[n] * vpb[n * HD + h];
        wr_hl(x1h, x1l, (size_t)b * 2048 + h, acc);
    }
    for (int h = tid; h < HD; h += 256)
        wr_hl(x1h, x1l, (size_t)b * 2048 + 1024 + h, h1cur[b * HD + h]);
}

// ---------------------------------------------------------------------------
// LSTM cell + LN fused with splitK gate reduction; optional X2 hi/lo output.
// ---------------------------------------------------------------------------
__global__ void lstm_ln_kernel(const float* __restrict__ gp, const float* __restrict__ bias,
                               const float* __restrict__ extra,
                               const float* __restrict__ cin, float* __restrict__ cout,
                               const float* __restrict__ gam, const float* __restrict__ bet,
                               float* __restrict__ hout,
                               __nv_bfloat16* __restrict__ x2h, __nv_bfloat16* __restrict__ x2l,
                               const float* __restrict__ h2cur)
{
    const size_t BG = (size_t)BB * G4;
    int b = blockIdx.x, tid = threadIdx.x;
    __shared__ float s_h[HD];
    __shared__ float s_red[64];
    __shared__ float s_mu, s_rstd;

    float sum = 0.f, sq = 0.f;
    for (int h = tid; h < HD; h += 256) {
        float g[4];
#pragma unroll
        for (int q = 0; q < 4; q++) {
            size_t idx = (size_t)b * G4 + q * 1024 + h;
            float v = gp[idx] + gp[BG + idx] + gp[2 * BG + idx] + gp[3 * BG + idx]
                    + bias[q * 1024 + h];
            if (extra) v += extra[idx];
            g[q] = v;
        }
        float c = sigf(g[1]) * cin[b * HD + h] + sigf(g[0]) * tanhf(g[2]);
        cout[b * HD + h] = c;
        float hv = sigf(g[3]) * tanhf(c);
        s_h[h] = hv;
        sum += hv; sq += hv * hv;
    }
#pragma unroll
    for (int o = 16; o > 0; o >>= 1) {
        sum += __shfl_down_sync(0xffffffffu, sum, o);
        sq  += __shfl_down_sync(0xffffffffu, sq,  o);
    }
    int warp = tid >> 5, lane = tid & 31;
    if (lane == 0) { s_red[warp] = sum; s_red[32 + warp] = sq; }
    __syncthreads();
    if (tid == 0) {
        float S = 0.f, Q = 0.f;
        for (int w = 0; w < 8; w++) { S += s_red[w]; Q += s_red[32 + w]; }
        float mu = S * (1.f / 1024.f);
        float var = Q * (1.f / 1024.f) - mu * mu;
        s_mu = mu; s_rstd = 1.f / sqrtf(var + 1e-5f);
    }
    __syncthreads();
    float mu = s_mu, rstd = s_rstd;
    for (int h = tid; h < HD; h += 256) {
        float v = (s_h[h] - mu) * rstd * gam[h] + bet[h];
        hout[b * HD + h] = v;
        if (x2h) wr_hl(x2h, x2l, (size_t)b * 2048 + h, v);
    }
    if (x2h)
        for (int h = tid; h < HD; h += 256)
            wr_hl(x2h, x2l, (size_t)b * 2048 + 1024 + h, h2cur[b * HD + h]);
}

// ---------------------------------------------------------------------------
// Launch
// ---------------------------------------------------------------------------
extern "C" void kernel_launch(void* const* d_in, const int* in_sizes, int n_in,
                              void* d_out, int out_size)
{
    (void)in_sizes; (void)n_in; (void)out_size;
    const float* V      = (const float*)d_in[0];
    const int*   y      = (const int*)  d_in[1];
    const float* embW   = (const float*)d_in[2];
    const float* Vp_W   = (const float*)d_in[3];
    const float* Vp_b   = (const float*)d_in[4];
    const float* attW   = (const float*)d_in[5];
    const float* attU   = (const float*)d_in[6];
    const float* attv   = (const float*)d_in[7];
    const float* l1_Wih = (const float*)d_in[8];
    const float* l1_Whh = (const float*)d_in[9];
    const float* l1_bih = (const float*)d_in[10];
    const float* l1_bhh = (const float*)d_in[11];
    const float* l2_Wih = (const float*)d_in[12];
    const float* l2_Whh = (const float*)d_in[13];
    const float* l2_bih = (const float*)d_in[14];
    const float* l2_bhh = (const float*)d_in[15];
    const float* n1_g   = (const float*)d_in[16];
    const float* n1_b   = (const float*)d_in[17];
    const float* n2_g   = (const float*)d_in[18];
    const float* n2_b   = (const float*)d_in[19];
    const float* ih_W   = (const float*)d_in[20];
    const float* ih_b   = (const float*)d_in[21];
    const float* ic_W   = (const float*)d_in[22];
    const float* ic_b   = (const float*)d_in[23];
    const float* proj_W = (const float*)d_in[24];
    float* out = (float*)d_out;

    float* buf = nullptr;
    cudaGetSymbolAddress((void**)&buf, g_buf);
    __nv_bfloat16* bf = nullptr;
    cudaGetSymbolAddress((void**)&bf, g_bf);

    float* VP  = buf + OFF_VP;
    float* UV  = buf + OFF_UV;
    float* FM  = buf + OFF_FM;
    float* H1  = buf + OFF_H1;
    float* C1  = buf + OFF_C1;
    float* C2  = buf + OFF_C2;
    float* H2A = buf + OFF_H2A;
    float* G1X = buf + OFF_G1X;
    float* B1  = buf + OFF_B1;
    float* B2  = buf + OFF_B2;
    float* GP  = buf + OFF_GP;
    float* WHP = buf + OFF_WHP;
    float* PF  = buf + OFF_PF;

    __nv_bfloat16 *W1h = bf + BO_W1,   *W1l = W1h + SZ_W1;
    __nv_bfloat16 *W2h = bf + BO_W2,   *W2l = W2h + SZ_W2;
    __nv_bfloat16 *EWh = bf + BO_EMBW, *EWl = EWh + SZ_EMBW;
    __nv_bfloat16 *PJh = bf + BO_PROJ, *PJl = PJh + SZ_PROJ;
    __nv_bfloat16 *AUh = bf + BO_ATTU, *AUl = AUh + SZ_ATTU;
    __nv_bfloat16 *VWh = bf + BO_VPW,  *VWl = VWh + SZ_VPW;
    __nv_bfloat16 *WXh = bf + BO_WX,   *WXl = WXh + SZ_WX;
    __nv_bfloat16 *Vh  = bf + BO_V,    *Vl  = Vh  + SZ_V;
    __nv_bfloat16 *VPh = bf + BO_VPB,  *VPl = VPh + SZ_VPB;
    __nv_bfloat16 *EXh = bf + BO_EMBX, *EXl = EXh + SZ_EMBX;
    __nv_bfloat16 *X1h = bf + BO_X1,   *X1l = X1h + SZ_X1;
    __nv_bfloat16 *X2h = bf + BO_X2,   *X2l = X2h + SZ_X2;
    __nv_bfloat16 *H2h = bf + BO_H2,   *H2l = H2h + SZ_H2;
    __nv_bfloat16 *Ph  = bf + BO_P,    *Pl  = Ph  + SZ_P;

    const int SLOT = BB * HD;
    auto nb = [](size_t tot) { return (unsigned)((tot + 255) / 256); };

    // ---- prologue: weight conversions ----
    build_wcat_hl<<<nb((size_t)G4 * 2048), 256>>>(W1h, W1l, l1_Wih, 1536, 512, l1_Whh);
    build_wcat_hl<<<nb((size_t)G4 * 2048), 256>>>(W2h, W2l, l2_Wih, 1024, 0, l2_Whh);
    cvt_hl<<<nb((size_t)NVP * EMB), 256>>>(embW, EMB, VOCAB, EMB, EWh, EWl, NVP);
    cvt_hl<<<nb(SZ_PROJ), 256>>>(proj_W, HD, EMB, HD, PJh, PJl, EMB);
    cvt_hl<<<nb(SZ_ATTU), 256>>>(attU, HD, ATT, HD, AUh, AUl, ATT);
    cvt_hl<<<nb(SZ_VPW), 256>>>(Vp_W, VD, HD, VD, VWh, VWl, HD);
    cvt_hl<<<nb(SZ_WX), 256>>>(l1_Wih, 1536, G4, EMB, WXh, WXl, G4);
    cvt_hl<<<nb(SZ_V), 256>>>(V, VD, BB * NN, VD, Vh, Vl, BB * NN);
    add_bias_kernel<<<16, 256>>>(B1, l1_bih, l1_bhh, G4);
    add_bias_kernel<<<16, 256>>>(B2, l2_bih, l2_bhh, G4);
    emb_gather_hl<<<nb(SZ_EMBX), 256>>>(EXh, EXl, embW, y);

    // Vp = V @ Vp_W^T + Vp_b : [6272,1024]
    hmma_gemm<0><<<dim3(HD / 128, NN, 1), 256>>>(Vh, Vl, VD, VWh, VWl, VD, VP, HD, VD, Vp_b);
    cvt_hl<<<nb(SZ_VPB), 256>>>(VP, HD, BB * NN, HD, VPh, VPl, BB * NN);
    feat_mean_kernel<<<nb((size_t)BB * HD), 256>>>(VP, FM);
    gemm_tile<1><<<dim3(HD / 32, 1, 1), 128>>>(FM, HD, ih_W, HD, H1, HD, HD, ih_b);
    gemm_tile<1><<<dim3(HD / 32, 1, 1), 128>>>(FM, HD, ic_W, HD, C1, HD, HD, ic_b);
    // Uv = Vp @ attU^T : [6272,512]
    hmma_gemm<0><<<dim3(ATT / 128, NN, 1), 256>>>(VPh, VPl, HD, AUh, AUl, HD, UV, ATT, HD, nullptr);
    // G1x = embx @ l1_Wih[:,:512]^T : [2432,4096]
    hmma_gemm<0><<<dim3(G4 / 128, TS, 1), 256>>>(EXh, EXl, EMB, WXh, WXl, EMB, G1X, G4, EMB, nullptr);

    cudaMemsetAsync(H2A, 0, (size_t)SLOT * sizeof(float), 0);
    cudaMemsetAsync(C2, 0, (size_t)SLOT * sizeof(float), 0);

    // ---- sequential decode ----
    for (int t = 0; t < TS; t++) {
        const float* h2c = H2A + (size_t)t * SLOT;
        gemm_tile<0><<<dim3(ATT / 32, 1, 4), 128>>>(h2c, HD, attW, HD, WHP, ATT, HD, nullptr);
        attn_kernel<<<BB, 256>>>(VP, UV, WHP, attv, H1 + (size_t)(t & 1) * SLOT, X1h, X1l);
        hmma_gemm<0><<<dim3(G4 / 128, 1, ZK), 256>>>(X1h, X1l, 2048, W1h, W1l, 2048,
                                                     GP, G4, 2048, nullptr);
        lstm_ln_kernel<<<BB, 256>>>(GP, B1, G1X + (size_t)t * BB * G4,
                                    C1 + (size_t)(t & 1) * SLOT,
                                    C1 + (size_t)((t + 1) & 1) * SLOT,
                                    n1_g, n1_b, H1 + (size_t)((t + 1) & 1) * SLOT,
                                    X2h, X2l, h2c);
        hmma_gemm<0><<<dim3(G4 / 128, 1, ZK), 256>>>(X2h, X2l, 2048, W2h, W2l, 2048,
                                                     GP, G4, 2048, nullptr);
        lstm_ln_kernel<<<BB, 256>>>(GP, B2, nullptr,
                                    C2 + (size_t)(t & 1) * SLOT,
                                    C2 + (size_t)((t + 1) & 1) * SLOT,
                                    n2_g, n2_b, H2A + (size_t)(t + 1) * SLOT,
                                    nullptr, nullptr, nullptr);
    }

    // ---- deferred output projection ----
    cvt_hl<<<nb(SZ_H2), 256>>>(H2A + SLOT, HD, TS * BB, HD, H2h, H2l, TS * BB);
    hmma_gemm<0><<<dim3(EMB / 128, TS, 1), 256>>>(H2h, H2l, HD, PJh, PJl, HD, PF, EMB, HD, nullptr);
    cvt_hl<<<nb(SZ_P), 256>>>(PF, EMB, TS * BB, EMB, Ph, Pl, TS * BB);
    hmma_gemm<3><<<dim3(NVP / 128, TS, 1), 256>>>(Ph, Pl, EMB, EWh, EWl, EMB, out, VOCAB, EMB, nullptr);
}

// round 6
// speedup vs baseline: 2.0784x; 1.0808x over previous
#include <cuda_runtime.h>
#include <cuda_bf16.h>
#include <cstdint>

// ---------------------------------------------------------------------------
// Problem constants
// ---------------------------------------------------------------------------
#define BB   128
#define TT   20
#define TS   19
#define NN   49
#define VOCAB 10000
#define NVP  10112       // VOCAB padded to 79*128
#define EMB  512
#define HD   1024
#define VD   512
#define ATT  512
#define G4   4096
#define ZK   4

// ---------------------------------------------------------------------------
// fp32 scratch
// ---------------------------------------------------------------------------
#define OFF_VP    ((size_t)0)
#define OFF_UV    (OFF_VP   + (size_t)BB*NN*HD)
#define OFF_FM    (OFF_UV   + (size_t)BB*NN*ATT)
#define OFF_H1    (OFF_FM   + (size_t)BB*HD)
#define OFF_C1    (OFF_H1   + (size_t)2*BB*HD)
#define OFF_C2    (OFF_C1   + (size_t)2*BB*HD)
#define OFF_H2A   (OFF_C2   + (size_t)2*BB*HD)
#define OFF_G1X   (OFF_H2A  + (size_t)TT*BB*HD)
#define OFF_B1    (OFF_G1X  + (size_t)TS*BB*G4)
#define OFF_B2    (OFF_B1   + (size_t)G4)
#define OFF_GP    (OFF_B2   + (size_t)G4)
#define OFF_WHP   (OFF_GP   + (size_t)ZK*BB*G4)
#define OFF_PF    (OFF_WHP  + (size_t)4*BB*ATT)
#define BUF_TOTAL (OFF_PF   + (size_t)TS*BB*EMB)
__device__ float g_buf[BUF_TOTAL];

// ---------------------------------------------------------------------------
// bf16 hi/lo scratch
// ---------------------------------------------------------------------------
#define SZ_W1   ((size_t)G4*2048)
#define SZ_W2   ((size_t)G4*2048)
#define SZ_EMBW ((size_t)NVP*EMB)
#define SZ_PROJ ((size_t)EMB*HD)
#define SZ_ATTU ((size_t)ATT*HD)
#define SZ_VPW  ((size_t)HD*VD)
#define SZ_WX   ((size_t)G4*EMB)
#define SZ_V    ((size_t)BB*NN*VD)
#define SZ_VPB  ((size_t)BB*NN*HD)
#define SZ_EMBX ((size_t)TS*BB*EMB)
#define SZ_X1   ((size_t)BB*2048)
#define SZ_X2   ((size_t)BB*2048)
#define SZ_H2   ((size_t)TS*BB*HD)
#define SZ_P    ((size_t)TS*BB*EMB)

#define BO_W1   ((size_t)0)
#define BO_W2   (BO_W1   + 2*SZ_W1)
#define BO_EMBW (BO_W2   + 2*SZ_W2)
#define BO_PROJ (BO_EMBW + 2*SZ_EMBW)
#define BO_ATTU (BO_PROJ + 2*SZ_PROJ)
#define BO_VPW  (BO_ATTU + 2*SZ_ATTU)
#define BO_WX   (BO_VPW  + 2*SZ_VPW)
#define BO_V    (BO_WX   + 2*SZ_WX)
#define BO_VPB  (BO_V    + 2*SZ_V)
#define BO_EMBX (BO_VPB  + 2*SZ_VPB)
#define BO_X1   (BO_EMBX + 2*SZ_EMBX)
#define BO_X2   (BO_X1   + 2*SZ_X1)
#define BO_H2   (BO_X2   + 2*SZ_X2)
#define BO_P    (BO_H2   + 2*SZ_H2)
#define BF_TOTAL (BO_P   + 2*SZ_P)
__device__ __nv_bfloat16 g_bf[BF_TOTAL];

__device__ __forceinline__ float sigf(float x) { return 1.f / (1.f + expf(-x)); }

__device__ __forceinline__ void wr_hl(__nv_bfloat16* hi, __nv_bfloat16* lo,
                                      size_t idx, float x) {
    __nv_bfloat16 h = __float2bfloat16(x);
    hi[idx] = h;
    lo[idx] = __float2bfloat16(x - __bfloat162float(h));
}

__device__ __forceinline__ uint32_t smem_u32(const void* p) {
    uint32_t a;
    asm("{ .reg .u64 t; cvta.to.shared.u64 t, %1; cvt.u32.u64 %0, t; }" : "=r"(a) : "l"(p));
    return a;
}

// ---------------------------------------------------------------------------
// HMMA primitives (base PTX, sm_80+)
// ---------------------------------------------------------------------------
#define LDSM4(r, a) \
    asm volatile("ldmatrix.sync.aligned.m8n8.x4.shared.b16 {%0,%1,%2,%3}, [%4];" \
        : "=r"((r)[0]), "=r"((r)[1]), "=r"((r)[2]), "=r"((r)[3]) : "r"(a))

#define MMA16816(d, a, b) \
    asm volatile("mma.sync.aligned.m16n8k16.row.col.f32.bf16.bf16.f32 " \
        "{%0,%1,%2,%3}, {%4,%5,%6,%7}, {%8,%9}, {%0,%1,%2,%3};" \
        : "+f"((d)[0]), "+f"((d)[1]), "+f"((d)[2]), "+f"((d)[3]) \
        : "r"((a)[0]), "r"((a)[1]), "r"((a)[2]), "r"((a)[3]), \
          "r"((b)[0]), "r"((b)[1]))

__device__ __forceinline__ void cpa16(uint32_t dst, const void* src) {
    asm volatile("cp.async.cg.shared.global [%0], [%1], 16;" :: "r"(dst), "l"(src));
}

// ---------------------------------------------------------------------------
// Pipelined HMMA GEMM: C[M,N] = A[M,K] @ B[N,K]^T, bf16 hi/lo 3-pass.
// BM=128, BN=128, BK=32, 256 threads (2x4 warps, warp tile 64x32).
// cp.async double-buffered: 2 stages x 4 arrays (Ahi, Alo, Bhi, Blo).
// MODE 0: fp32 store (+bias), splitK z partials.  MODE 3: logits permuted store.
// ---------------------------------------------------------------------------
#define SAK 40
#define ARR_BYTES (128 * SAK * 2)       // 10240
#define STG_BYTES (4 * ARR_BYTES)       // 40960
#define HM_SMEM   (2 * STG_BYTES)       // 81920

template <int MODE>
__global__ void __launch_bounds__(256)
hmma_gemm(const __nv_bfloat16* __restrict__ Ahi, const __nv_bfloat16* __restrict__ Alo, int lda,
          const __nv_bfloat16* __restrict__ Bhi, const __nv_bfloat16* __restrict__ Blo, int ldb,
          float* __restrict__ C, int N, int K,
          const float* __restrict__ bias)
{
    extern __shared__ __nv_bfloat16 smh[];
    uint32_t sb = smem_u32(smh);

    const int tid  = threadIdx.x;
    const int lane = tid & 31, wid = tid >> 5;
    const int wm = wid & 1;
    const int wn = wid >> 1;
    const int n0 = blockIdx.x * 128, m0 = blockIdx.y * 128;
    const int kchunk = K / gridDim.z;
    const int kbeg   = blockIdx.z * kchunk;
    const int niter  = kchunk >> 5;

    const int lr = tid >> 2;          // 0..63
    const int lc = (tid & 3) * 8;     // 0/8/16/24

    float acc[4][4][4];
#pragma unroll
    for (int i = 0; i < 4; i++)
#pragma unroll
        for (int j = 0; j < 4; j++)
#pragma unroll
            for (int q = 0; q < 4; q++) acc[i][j][q] = 0.f;

    const int arow = wm * 64 + (lane & 15);
    const int acol = (lane >> 4) * 8;
    const int brow = wn * 32 + ((lane >> 4) * 8) + (lane & 7);
    const int bcol = ((lane >> 3) & 1) * 8;
    const uint32_t a_off = (uint32_t)(arow * SAK + acol) * 2;
    const uint32_t b_off = (uint32_t)(brow * SAK + bcol) * 2;

    // prefetch stage 0
    {
        const int kb = kbeg;
#pragma unroll
        for (int i = 0; i < 2; i++) {
            int r = lr + 64 * i;
            uint32_t off = (uint32_t)(r * SAK + lc) * 2;
            cpa16(sb + 0 * ARR_BYTES + off, Ahi + (size_t)(m0 + r) * lda + kb + lc);
            cpa16(sb + 1 * ARR_BYTES + off, Alo + (size_t)(m0 + r) * lda + kb + lc);
            cpa16(sb + 2 * ARR_BYTES + off, Bhi + (size_t)(n0 + r) * ldb + kb + lc);
            cpa16(sb + 3 * ARR_BYTES + off, Blo + (size_t)(n0 + r) * ldb + kb + lc);
        }
        asm volatile("cp.async.commit_group;" ::: "memory");
    }

    for (int it = 0; it < niter; it++) {
        if (it + 1 < niter) {
            const int kb = kbeg + (it + 1) * 32;
            uint32_t base = sb + ((it + 1) & 1) * STG_BYTES;
#pragma unroll
            for (int i = 0; i < 2; i++) {
                int r = lr + 64 * i;
                uint32_t off = (uint32_t)(r * SAK + lc) * 2;
                cpa16(base + 0 * ARR_BYTES + off, Ahi + (size_t)(m0 + r) * lda + kb + lc);
                cpa16(base + 1 * ARR_BYTES + off, Alo + (size_t)(m0 + r) * lda + kb + lc);
                cpa16(base + 2 * ARR_BYTES + off, Bhi + (size_t)(n0 + r) * ldb + kb + lc);
                cpa16(base + 3 * ARR_BYTES + off, Blo + (size_t)(n0 + r) * ldb + kb + lc);
            }
            asm volatile("cp.async.commit_group;" ::: "memory");
            asm volatile("cp.async.wait_group 1;" ::: "memory");
        } else {
            asm volatile("cp.async.wait_group 0;" ::: "memory");
        }
        __syncthreads();

        const uint32_t sbase = sb + (it & 1) * STG_BYTES;
        const uint32_t a_h = sbase + a_off;
        const uint32_t a_l = sbase + 1 * ARR_BYTES + a_off;
        const uint32_t b_h = sbase + 2 * ARR_BYTES + b_off;
        const uint32_t b_l = sbase + 3 * ARR_BYTES + b_off;

#pragma unroll
        for (int s = 0; s < 2; s++) {
            const uint32_t so = s * 16 * 2;
            uint32_t ah[4][4], al[4][4], bh[4][2], bl[4][2];
#pragma unroll
            for (int mt = 0; mt < 4; mt++) {
                LDSM4(ah[mt], a_h + so + mt * 16 * SAK * 2);
                LDSM4(al[mt], a_l + so + mt * 16 * SAK * 2);
            }
#pragma unroll
            for (int p = 0; p < 2; p++) {
                uint32_t r4[4];
                LDSM4(r4, b_h + so + p * 16 * SAK * 2);
                bh[p * 2][0] = r4[0]; bh[p * 2][1] = r4[1];
                bh[p * 2 + 1][0] = r4[2]; bh[p * 2 + 1][1] = r4[3];
                LDSM4(r4, b_l + so + p * 16 * SAK * 2);
                bl[p * 2][0] = r4[0]; bl[p * 2][1] = r4[1];
                bl[p * 2 + 1][0] = r4[2]; bl[p * 2 + 1][1] = r4[3];
            }
#pragma unroll
            for (int mt = 0; mt < 4; mt++)
#pragma unroll
                for (int nt = 0; nt < 4; nt++) {
                    MMA16816(acc[mt][nt], ah[mt], bh[nt]);
                    MMA16816(acc[mt][nt], ah[mt], bl[nt]);
                    MMA16816(acc[mt][nt], al[mt], bh[nt]);
                }
        }
        __syncthreads();
    }

    // epilogue
    const size_t Mtot = (size_t)gridDim.y * 128;
    float* Cb = C + (gridDim.z > 1 ? (size_t)blockIdx.z * Mtot * N : 0);
    const int er = (lane >> 2);
    const int ec = (lane & 3) * 2;
#pragma unroll
    for (int mt = 0; mt < 4; mt++) {
#pragma unroll
        for (int nt = 0; nt < 4; nt++) {
            int n = n0 + wn * 32 + nt * 8 + ec;
            float b0 = 0.f, b1 = 0.f;
            if (MODE == 0 && bias) { b0 = bias[n]; b1 = bias[n + 1]; }
#pragma unroll
            for (int h = 0; h < 2; h++) {
                int m = m0 + wm * 64 + mt * 16 + er + h * 8;
                float v0 = acc[mt][nt][h * 2 + 0] + b0;
                float v1 = acc[mt][nt][h * 2 + 1] + b1;
                if (MODE == 0) {
                    *(float2*)&Cb[(size_t)m * N + n] = make_float2(v0, v1);
                } else {
                    int b = m & 127, t = m >> 7;
                    float* o = &Cb[((size_t)b * TS + t) * VOCAB + n];
                    if (n < VOCAB) o[0] = v0;
                    if (n + 1 < VOCAB) o[1] = v1;
                }
            }
        }
    }
}

// ---------------------------------------------------------------------------
// fp32 SGEMM (small: ih/ic init, per-step wh) — f32x2
// ---------------------------------------------------------------------------
__device__ __forceinline__ void fma2(unsigned long long& d, unsigned long long a,
                                     unsigned long long b) {
    asm("fma.rn.f32x2 %0, %1, %2, %0;" : "+l"(d) : "l"(a), "l"(b));
}
__device__ __forceinline__ unsigned long long splat2(float x) {
    unsigned long long r;
    unsigned u = __float_as_uint(x);
    asm("mov.b64 %0, {%1, %1};" : "=l"(r) : "r"(u));
    return r;
}

template <int MODE>  // 0: store(+bias, splitK), 1: tanh(acc+bias)
__global__ void __launch_bounds__(128)
gemm_tile(const float* __restrict__ A, int lda,
          const float* __restrict__ W, int ldw,
          float* __restrict__ C, int N, int K,
          const float* __restrict__ bias)
{
    __shared__ float As[32][132];
    __shared__ float Ws[32][36];
    const int tid = threadIdx.x;
    const int n0 = blockIdx.x * 32, m0 = blockIdx.y * 128;
    const int kchunk = K / gridDim.z;
    const int kbeg = blockIdx.z * kchunk;
    const float* Ab = A + (size_t)m0 * lda;
    const int a_c = tid & 7, a_r = tid >> 3;
    const int ty = tid >> 3, tx = tid & 7;

    unsigned long long acc[4][4];
#pragma unroll
    for (int i = 0; i < 4; i++)
#pragma unroll
        for (int j = 0; j < 4; j++) acc[i][j] = 0ull;

    for (int kb = kbeg; kb < kbeg + kchunk; kb += 32) {
#pragma unroll
        for (int i = 0; i < 8; i++) {
            int r = a_r + 16 * i;
            float4 v = *reinterpret_cast<const float4*>(Ab + (size_t)r * lda + kb + 4 * a_c);
            As[4 * a_c + 0][r] = v.x; As[4 * a_c + 1][r] = v.y;
            As[4 * a_c + 2][r] = v.z; As[4 * a_c + 3][r] = v.w;
        }
#pragma unroll
        for (int i = 0; i < 2; i++) {
            int idx = tid + 128 * i;
            int r = idx >> 3, c = idx & 7;
            int n = n0 + r;
            float4 v = make_float4(0.f, 0.f, 0.f, 0.f);
            if (n < N) v = *reinterpret_cast<const float4*>(W + (size_t)n * ldw + kb + 4 * c);
            Ws[4 * c + 0][r] = v.x; Ws[4 * c + 1][r] = v.y;
            Ws[4 * c + 2][r] = v.z; Ws[4 * c + 3][r] = v.w;
        }
        __syncthreads();
#pragma unroll
        for (int kk = 0; kk < 32; kk++) {
            double2 a01 = *reinterpret_cast<const double2*>(&As[kk][ty * 8]);
            double2 a23 = *reinterpret_cast<const double2*>(&As[kk][ty * 8 + 4]);
            unsigned long long av[4] = {__double_as_longlong(a01.x), __double_as_longlong(a01.y),
                                        __double_as_longlong(a23.x), __double_as_longlong(a23.y)};
            float4 w = *reinterpret_cast<const float4*>(&Ws[kk][tx * 4]);
            unsigned long long wv[4] = {splat2(w.x), splat2(w.y), splat2(w.z), splat2(w.w)};
#pragma unroll
            for (int i = 0; i < 4; i++)
#pragma unroll
                for (int j = 0; j < 4; j++) fma2(acc[i][j], av[i], wv[j]);
        }
        __syncthreads();
    }

    const size_t Mtot = (size_t)gridDim.y * 128;
    float* Cb = C + (gridDim.z > 1 ? (size_t)blockIdx.z * Mtot * N : 0);
#pragma unroll
    for (int i = 0; i < 4; i++) {
        int mA = m0 + ty * 8 + 2 * i;
#pragma unroll
        for (int j = 0; j < 4; j++) {
            int n = n0 + tx * 4 + j;
            if (n >= N) continue;
            float2 p = *reinterpret_cast<float2*>(&acc[i][j]);
            float v0 = p.x, v1 = p.y;
            if (MODE == 1) { v0 = tanhf(v0 + bias[n]); v1 = tanhf(v1 + bias[n]); }
            else if (bias) { v0 += bias[n]; v1 += bias[n]; }
            Cb[(size_t)mA * N + n] = v0;
            Cb[(size_t)(mA + 1) * N + n] = v1;
        }
    }
}

// ---------------------------------------------------------------------------
// Prep / conversion kernels
// ---------------------------------------------------------------------------
__global__ void cvt_hl(const float* __restrict__ src, int ld, int rows, int cols,
                       __nv_bfloat16* __restrict__ hi, __nv_bfloat16* __restrict__ lo,
                       int rowsPad)
{
    int idx = blockIdx.x * 256 + threadIdx.x;
    if (idx >= rowsPad * cols) return;
    int r = idx / cols, c = idx - r * cols;
    float x = (r < rows) ? src[(size_t)r * ld + c] : 0.f;
    wr_hl(hi, lo, idx, x);
}

__global__ void build_wcat_hl(__nv_bfloat16* __restrict__ hi, __nv_bfloat16* __restrict__ lo,
                              const float* __restrict__ Wih, int ld_ih, int coff,
                              const float* __restrict__ Whh)
{
    int idx = blockIdx.x * 256 + threadIdx.x;
    if (idx >= G4 * 2048) return;
    int n = idx >> 11, k = idx & 2047;
    float x = (k < 1024) ? Wih[(size_t)n * ld_ih + coff + k]
                         : Whh[(size_t)n * 1024 + (k - 1024)];
    wr_hl(hi, lo, idx, x);
}

__global__ void add_bias_kernel(float* __restrict__ dst, const float* __restrict__ a,
                                const float* __restrict__ b, int n)
{
    int i = blockIdx.x * 256 + threadIdx.x;
    if (i < n) dst[i] = a[i] + b[i];
}

__global__ void emb_gather_hl(__nv_bfloat16* __restrict__ hi, __nv_bfloat16* __restrict__ lo,
                              const float* __restrict__ embW, const int* __restrict__ y)
{
    int idx = blockIdx.x * 256 + threadIdx.x;
    if (idx >= TS * BB * EMB) return;
    int e = idx & 511;
    int b = (idx >> 9) & 127;
    int t = idx >> 16;
    wr_hl(hi, lo, idx, embW[(size_t)y[b * TT + t] * EMB + e]);
}

__global__ void feat_mean_kernel(const float* __restrict__ Vp, float* __restrict__ fm)
{
    int idx = blockIdx.x * 256 + threadIdx.x;
    if (idx >= BB * HD) return;
    int b = idx >> 10, h = idx & 1023;
    const float* p = Vp + (size_t)b * NN * HD + h;
    float s = 0.f;
#pragma unroll 7
    for (int n = 0; n < NN; n++) s += p[n * HD];
    fm[idx] = s * (1.f / 49.f);
}

// ---------------------------------------------------------------------------
// Attention: sums wh partials, e, softmax, ctx; writes X1 = [ctx | h1] hi/lo
// ---------------------------------------------------------------------------
__global__ void attn_kernel(const float* __restrict__ Vp, const float* __restrict__ Uv,
                            const float* __restrict__ whp, const float* __restrict__ attv,
                            const float* __restrict__ h1cur,
                            __nv_bfloat16* __restrict__ x1h, __nv_bfloat16* __restrict__ x1l)
{
    int b = blockIdx.x, tid = threadIdx.x;
    __shared__ float s_wh[ATT];
    __shared__ float s_e[NN];

    for (int a = tid; a < ATT; a += 256) {
        int o = b * ATT + a;
        s_wh[a] = whp[o] + whp[BB * ATT + o] + whp[2 * BB * ATT + o] + whp[3 * BB * ATT + o];
    }
    __syncthreads();

    int warp = tid >> 5, lane = tid & 31;
    for (int n = warp; n < NN; n += 8) {
        const float* uv = Uv + ((size_t)b * NN + n) * ATT;
        float s = 0.f;
        for (int a = lane; a < ATT; a += 32) s += tanhf(s_wh[a] + uv[a]) * attv[a];
#pragma unroll
        for (int o = 16; o > 0; o >>= 1) s += __shfl_down_sync(0xffffffffu, s, o);
        if (lane == 0) s_e[n] = s;
    }
    __syncthreads();

    if (tid == 0) {
        float m = -1e30f;
        for (int n = 0; n < NN; n++) m = fmaxf(m, s_e[n]);
        float S = 0.f;
        for (int n = 0; n < NN; n++) { float v = expf(s_e[n] - m); s_e[n] = v; S += v; }
        float inv = 1.f / S;
        for (int n = 0; n < NN; n++) s_e[n] *= inv;
    }
    __syncthreads();

    const float* vpb = Vp + (size_t)b * NN * HD;
    for (int h = tid; h < HD; h += 256) {
        float acc = 0.f;
#pragma unroll 7
        for (int n = 0; n < NN; n++) acc += s_e[n] * vpb[n * HD + h];
        wr_hl(x1h, x1l, (size_t)b * 2048 + h, acc);
    }
    for (int h = tid; h < HD; h += 256)
        wr_hl(x1h, x1l, (size_t)b * 2048 + 1024 + h, h1cur[b * HD + h]);
}

// ---------------------------------------------------------------------------
// LSTM cell + LN fused with splitK gate reduction; optional X2 hi/lo output.
// ---------------------------------------------------------------------------
__global__ void lstm_ln_kernel(const float* __restrict__ gp, const float* __restrict__ bias,
                               const float* __restrict__ extra,
                               const float* __restrict__ cin, float* __restrict__ cout,
                               const float* __restrict__ gam, const float* __restrict__ bet,
                               float* __restrict__ hout,
                               __nv_bfloat16* __restrict__ x2h, __nv_bfloat16* __restrict__ x2l,
                               const float* __restrict__ h2cur)
{
    const size_t BG = (size_t)BB * G4;
    int b = blockIdx.x, tid = threadIdx.x;
    __shared__ float s_h[HD];
    __shared__ float s_red[64];
    __shared__ float s_mu, s_rstd;

    float sum = 0.f, sq = 0.f;
    for (int h = tid; h < HD; h += 256) {
        float g[4];
#pragma unroll
        for (int q = 0; q < 4; q++) {
            size_t idx = (size_t)b * G4 + q * 1024 + h;
            float v = gp[idx] + gp[BG + idx] + gp[2 * BG + idx] + gp[3 * BG + idx]
                    + bias[q * 1024 + h];
            if (extra) v += extra[idx];
            g[q] = v;
        }
        float c = sigf(g[1]) * cin[b * HD + h] + sigf(g[0]) * tanhf(g[2]);
        cout[b * HD + h] = c;
        float hv = sigf(g[3]) * tanhf(c);
        s_h[h] = hv;
        sum += hv; sq += hv * hv;
    }
#pragma unroll
    for (int o = 16; o > 0; o >>= 1) {
        sum += __shfl_down_sync(0xffffffffu, sum, o);
        sq  += __shfl_down_sync(0xffffffffu, sq,  o);
    }
    int warp = tid >> 5, lane = tid & 31;
    if (lane == 0) { s_red[warp] = sum; s_red[32 + warp] = sq; }
    __syncthreads();
    if (tid == 0) {
        float S = 0.f, Q = 0.f;
        for (int w = 0; w < 8; w++) { S += s_red[w]; Q += s_red[32 + w]; }
        float mu = S * (1.f / 1024.f);
        float var = Q * (1.f / 1024.f) - mu * mu;
        s_mu = mu; s_rstd = 1.f / sqrtf(var + 1e-5f);
    }
    __syncthreads();
    float mu = s_mu, rstd = s_rstd;
    for (int h = tid; h < HD; h += 256) {
        float v = (s_h[h] - mu) * rstd * gam[h] + bet[h];
        hout[b * HD + h] = v;
        if (x2h) wr_hl(x2h, x2l, (size_t)b * 2048 + h, v);
    }
    if (x2h)
        for (int h = tid; h < HD; h += 256)
            wr_hl(x2h, x2l, (size_t)b * 2048 + 1024 + h, h2cur[b * HD + h]);
}

// ---------------------------------------------------------------------------
// Launch
// ---------------------------------------------------------------------------
extern "C" void kernel_launch(void* const* d_in, const int* in_sizes, int n_in,
                              void* d_out, int out_size)
{
    (void)in_sizes; (void)n_in; (void)out_size;
    const float* V      = (const float*)d_in[0];
    const int*   y      = (const int*)  d_in[1];
    const float* embW   = (const float*)d_in[2];
    const float* Vp_W   = (const float*)d_in[3];
    const float* Vp_b   = (const float*)d_in[4];
    const float* attW   = (const float*)d_in[5];
    const float* attU   = (const float*)d_in[6];
    const float* attv   = (const float*)d_in[7];
    const float* l1_Wih = (const float*)d_in[8];
    const float* l1_Whh = (const float*)d_in[9];
    const float* l1_bih = (const float*)d_in[10];
    const float* l1_bhh = (const float*)d_in[11];
    const float* l2_Wih = (const float*)d_in[12];
    const float* l2_Whh = (const float*)d_in[13];
    const float* l2_bih = (const float*)d_in[14];
    const float* l2_bhh = (const float*)d_in[15];
    const float* n1_g   = (const float*)d_in[16];
    const float* n1_b   = (const float*)d_in[17];
    const float* n2_g   = (const float*)d_in[18];
    const float* n2_b   = (const float*)d_in[19];
    const float* ih_W   = (const float*)d_in[20];
    const float* ih_b   = (const float*)d_in[21];
    const float* ic_W   = (const float*)d_in[22];
    const float* ic_b   = (const float*)d_in[23];
    const float* proj_W = (const float*)d_in[24];
    float* out = (float*)d_out;

    cudaFuncSetAttribute(hmma_gemm<0>, cudaFuncAttributeMaxDynamicSharedMemorySize, HM_SMEM);
    cudaFuncSetAttribute(hmma_gemm<3>, cudaFuncAttributeMaxDynamicSharedMemorySize, HM_SMEM);

    float* buf = nullptr;
    cudaGetSymbolAddress((void**)&buf, g_buf);
    __nv_bfloat16* bf = nullptr;
    cudaGetSymbolAddress((void**)&bf, g_bf);

    float* VP  = buf + OFF_VP;
    float* UV  = buf + OFF_UV;
    float* FM  = buf + OFF_FM;
    float* H1  = buf + OFF_H1;
    float* C1  = buf + OFF_C1;
    float* C2  = buf + OFF_C2;
    float* H2A = buf + OFF_H2A;
    float* G1X = buf + OFF_G1X;
    float* B1  = buf + OFF_B1;
    float* B2  = buf + OFF_B2;
    float* GP  = buf + OFF_GP;
    float* WHP = buf + OFF_WHP;
    float* PF  = buf + OFF_PF;

    __nv_bfloat16 *W1h = bf + BO_W1,   *W1l = W1h + SZ_W1;
    __nv_bfloat16 *W2h = bf + BO_W2,   *W2l = W2h + SZ_W2;
    __nv_bfloat16 *EWh = bf + BO_EMBW, *EWl = EWh + SZ_EMBW;
    __nv_bfloat16 *PJh = bf + BO_PROJ, *PJl = PJh + SZ_PROJ;
    __nv_bfloat16 *AUh = bf + BO_ATTU, *AUl = AUh + SZ_ATTU;
    __nv_bfloat16 *VWh = bf + BO_VPW,  *VWl = VWh + SZ_VPW;
    __nv_bfloat16 *WXh = bf + BO_WX,   *WXl = WXh + SZ_WX;
    __nv_bfloat16 *Vh  = bf + BO_V,    *Vl  = Vh  + SZ_V;
    __nv_bfloat16 *VPh = bf + BO_VPB,  *VPl = VPh + SZ_VPB;
    __nv_bfloat16 *EXh = bf + BO_EMBX, *EXl = EXh + SZ_EMBX;
    __nv_bfloat16 *X1h = bf + BO_X1,   *X1l = X1h + SZ_X1;
    __nv_bfloat16 *X2h = bf + BO_X2,   *X2l = X2h + SZ_X2;
    __nv_bfloat16 *H2h = bf + BO_H2,   *H2l = H2h + SZ_H2;
    __nv_bfloat16 *Ph  = bf + BO_P,    *Pl  = Ph  + SZ_P;

    const int SLOT = BB * HD;
    auto nb = [](size_t tot) { return (unsigned)((tot + 255) / 256); };

    // ---- prologue (ordered so the 6th launch is a representative hmma_gemm
    //      for ncu capture: -s 5 -c 1 profiles the G1X GEMM) ----
    build_wcat_hl<<<nb((size_t)G4 * 2048), 256>>>(W1h, W1l, l1_Wih, 1536, 512, l1_Whh); // 1
    build_wcat_hl<<<nb((size_t)G4 * 2048), 256>>>(W2h, W2l, l2_Wih, 1024, 0, l2_Whh);   // 2
    emb_gather_hl<<<nb(SZ_EMBX), 256>>>(EXh, EXl, embW, y);                              // 3
    cvt_hl<<<nb(SZ_WX), 256>>>(l1_Wih, 1536, G4, EMB, WXh, WXl, G4);                     // 4
    add_bias_kernel<<<32, 256>>>(B1, l1_bih, l1_bhh, G4);                                // 5
    // 6: PROFILED — G1x = embx @ l1_Wih[:,:512]^T : [2432,4096], K=512
    hmma_gemm<0><<<dim3(G4 / 128, TS, 1), 256, HM_SMEM>>>(EXh, EXl, EMB, WXh, WXl, EMB,
                                                          G1X, G4, EMB, nullptr);

    add_bias_kernel<<<32, 256>>>(B2, l2_bih, l2_bhh, G4);
    cvt_hl<<<nb((size_t)NVP * EMB), 256>>>(embW, EMB, VOCAB, EMB, EWh, EWl, NVP);
    cvt_hl<<<nb(SZ_PROJ), 256>>>(proj_W, HD, EMB, HD, PJh, PJl, EMB);
    cvt_hl<<<nb(SZ_ATTU), 256>>>(attU, HD, ATT, HD, AUh, AUl, ATT);
    cvt_hl<<<nb(SZ_VPW), 256>>>(Vp_W, VD, HD, VD, VWh, VWl, HD);
    cvt_hl<<<nb(SZ_V), 256>>>(V, VD, BB * NN, VD, Vh, Vl, BB * NN);

    // Vp = V @ Vp_W^T + Vp_b : [6272,1024]
    hmma_gemm<0><<<dim3(HD / 128, NN, 1), 256, HM_SMEM>>>(Vh, Vl, VD, VWh, VWl, VD,
                                                          VP, HD, VD, Vp_b);
    cvt_hl<<<nb(SZ_VPB), 256>>>(VP, HD, BB * NN, HD, VPh, VPl, BB * NN);
    feat_mean_kernel<<<nb((size_t)BB * HD), 256>>>(VP, FM);
    gemm_tile<1><<<dim3(HD / 32, 1, 1), 128>>>(FM, HD, ih_W, HD, H1, HD, HD, ih_b);
    gemm_tile<1><<<dim3(HD / 32, 1, 1), 128>>>(FM, HD, ic_W, HD, C1, HD, HD, ic_b);
    // Uv = Vp @ attU^T : [6272,512]
    hmma_gemm<0><<<dim3(ATT / 128, NN, 1), 256, HM_SMEM>>>(VPh, VPl, HD, AUh, AUl, HD,
                                                           UV, ATT, HD, nullptr);

    cudaMemsetAsync(H2A, 0, (size_t)SLOT * sizeof(float), 0);
    cudaMemsetAsync(C2, 0, (size_t)SLOT * sizeof(float), 0);

    // ---- sequential decode ----
    for (int t = 0; t < TS; t++) {
        const float* h2c = H2A + (size_t)t * SLOT;
        gemm_tile<0><<<dim3(ATT / 32, 1, 4), 128>>>(h2c, HD, attW, HD, WHP, ATT, HD, nullptr);
        attn_kernel<<<BB, 256>>>(VP, UV, WHP, attv, H1 + (size_t)(t & 1) * SLOT, X1h, X1l);
        hmma_gemm<0><<<dim3(G4 / 128, 1, ZK), 256, HM_SMEM>>>(X1h, X1l, 2048, W1h, W1l, 2048,
                                                              GP, G4, 2048, nullptr);
        lstm_ln_kernel<<<BB, 256>>>(GP, B1, G1X + (size_t)t * BB * G4,
                                    C1 + (size_t)(t & 1) * SLOT,
                                    C1 + (size_t)((t + 1) & 1) * SLOT,
                                    n1_g, n1_b, H1 + (size_t)((t + 1) & 1) * SLOT,
                                    X2h, X2l, h2c);
        hmma_gemm<0><<<dim3(G4 / 128, 1, ZK), 256, HM_SMEM>>>(X2h, X2l, 2048, W2h, W2l, 2048,
                                                              GP, G4, 2048, nullptr);
        lstm_ln_kernel<<<BB, 256>>>(GP, B2, nullptr,
                                    C2 + (size_t)(t & 1) * SLOT,
                                    C2 + (size_t)((t + 1) & 1) * SLOT,
                                    n2_g, n2_b, H2A + (size_t)(t + 1) * SLOT,
                                    nullptr, nullptr, nullptr);
    }

    // ---- deferred output projection ----
    cvt_hl<<<nb(SZ_H2), 256>>>(H2A + SLOT, HD, TS * BB, HD, H2h, H2l, TS * BB);
    hmma_gemm<0><<<dim3(EMB / 128, TS, 1), 256, HM_SMEM>>>(H2h, H2l, HD, PJh, PJl, HD,
                                                           PF, EMB, HD, nullptr);
    cvt_hl<<<nb(SZ_P), 256>>>(PF, EMB, TS * BB, EMB, Ph, Pl, TS * BB);
    hmma_gemm<3><<<dim3(NVP / 128, TS, 1), 256, HM_SMEM>>>(Ph, Pl, EMB, EWh, EWl, EMB,
                                                           out, VOCAB, EMB, nullptr);
}